// round 1
// baseline (speedup 1.0000x reference)
#include <cuda_runtime.h>
#include <math.h>

// Problem constants (fixed shapes for this problem instance)
#define S_LEN  1024
#define DM     4096
#define NH     32
#define HD     128
#define CACHE  2048

// Scratch (device globals: allocation-free rule)
__device__ float g_xn[S_LEN * DM];
__device__ float g_q [S_LEN * DM];
__device__ float g_k [S_LEN * DM];
__device__ float g_v [S_LEN * DM];
__device__ float g_at[S_LEN * DM];

// ---------------------------------------------------------------------------
// RMSNorm: one block per row (4096 elems), 256 threads
// ---------------------------------------------------------------------------
__global__ void rmsnorm_kernel(const float* __restrict__ xs,
                               const float* __restrict__ w)
{
    const int row = blockIdx.x;
    const int tid = threadIdx.x;
    const float* x = xs + (size_t)row * DM;
    float* y = g_xn + (size_t)row * DM;

    float ss = 0.f;
#pragma unroll
    for (int i = 0; i < 4; i++) {
        float4 v = *(const float4*)(x + (i * 256 + tid) * 4);
        ss += v.x * v.x + v.y * v.y + v.z * v.z + v.w * v.w;
    }
#pragma unroll
    for (int off = 16; off; off >>= 1)
        ss += __shfl_xor_sync(0xffffffffu, ss, off);

    __shared__ float red[8];
    __shared__ float s_inv;
    if ((tid & 31) == 0) red[tid >> 5] = ss;
    __syncthreads();
    if (tid == 0) {
        float t = 0.f;
#pragma unroll
        for (int i = 0; i < 8; i++) t += red[i];
        s_inv = rsqrtf(t / (float)DM + 1e-6f);
    }
    __syncthreads();
    const float inv = s_inv;
#pragma unroll
    for (int i = 0; i < 4; i++) {
        int base = (i * 256 + tid) * 4;
        float4 v = *(const float4*)(x + base);
        float4 g = *(const float4*)(w + base);
        v.x = v.x * inv * g.x;
        v.y = v.y * inv * g.y;
        v.z = v.z * inv * g.z;
        v.w = v.w * inv * g.w;
        *(float4*)(y + base) = v;
    }
}

// ---------------------------------------------------------------------------
// SGEMM (NT): C[M,N] = A[M,K] * B[N,K]^T, all row-major, K contiguous.
// Tile 128x128x16, 256 threads, 8x8 per-thread microtile.
// Grid: (N/128, M/128). M,N,K multiples of 128/16 (guaranteed here).
// ---------------------------------------------------------------------------
__global__ void __launch_bounds__(256, 2)
sgemm_nt(const float* __restrict__ A, const float* __restrict__ B,
         float* __restrict__ C, int N, int K)
{
    __shared__ float As[16][128];
    __shared__ float Bs[16][128];

    const int tid = threadIdx.x;
    const int tx = tid & 15;
    const int ty = tid >> 4;

    const float* Ab = A + (size_t)blockIdx.y * 128 * K;
    const float* Bb = B + (size_t)blockIdx.x * 128 * K;

    float c[8][8];
#pragma unroll
    for (int i = 0; i < 8; i++)
#pragma unroll
        for (int j = 0; j < 8; j++) c[i][j] = 0.f;

    const int lrow = tid >> 2;        // 0..63
    const int lcol = (tid & 3) << 2;  // 0,4,8,12

    for (int k0 = 0; k0 < K; k0 += 16) {
#pragma unroll
        for (int p = 0; p < 2; p++) {
            int row = lrow + p * 64;
            float4 va = *(const float4*)(Ab + (size_t)row * K + k0 + lcol);
            As[lcol + 0][row] = va.x;
            As[lcol + 1][row] = va.y;
            As[lcol + 2][row] = va.z;
            As[lcol + 3][row] = va.w;
            float4 vb = *(const float4*)(Bb + (size_t)row * K + k0 + lcol);
            Bs[lcol + 0][row] = vb.x;
            Bs[lcol + 1][row] = vb.y;
            Bs[lcol + 2][row] = vb.z;
            Bs[lcol + 3][row] = vb.w;
        }
        __syncthreads();
#pragma unroll
        for (int kk = 0; kk < 16; kk++) {
            float a[8], b[8];
            *(float4*)&a[0] = *(const float4*)&As[kk][ty * 8];
            *(float4*)&a[4] = *(const float4*)&As[kk][ty * 8 + 4];
            *(float4*)&b[0] = *(const float4*)&Bs[kk][tx * 8];
            *(float4*)&b[4] = *(const float4*)&Bs[kk][tx * 8 + 4];
#pragma unroll
            for (int i = 0; i < 8; i++)
#pragma unroll
                for (int j = 0; j < 8; j++)
                    c[i][j] = fmaf(a[i], b[j], c[i][j]);
        }
        __syncthreads();
    }

    const int crow0 = blockIdx.y * 128 + ty * 8;
    const int ccol0 = blockIdx.x * 128 + tx * 8;
#pragma unroll
    for (int i = 0; i < 8; i++) {
        float* dst = C + (size_t)(crow0 + i) * N + ccol0;
        *(float4*)(dst + 0) = make_float4(c[i][0], c[i][1], c[i][2], c[i][3]);
        *(float4*)(dst + 4) = make_float4(c[i][4], c[i][5], c[i][6], c[i][7]);
    }
}

// ---------------------------------------------------------------------------
// RoPE (in-place) on a [S, NH, HD] fp32 buffer, position offset = CACHE
// ---------------------------------------------------------------------------
__global__ void rope_kernel(float* __restrict__ buf)
{
    int idx = blockIdx.x * blockDim.x + threadIdx.x;  // S*NH*64 threads
    int i = idx & 63;
    int h = (idx >> 6) & (NH - 1);
    int s = idx >> 11;

    float pos = (float)(s + CACHE);
    // theta^(-i/64) = 2^(-i * log2(10000)/64)
    float inv_freq = exp2f(-(float)i * (13.287712379549449f / 64.f));
    float ang = pos * inv_freq;
    float sn, cs;
    sincosf(ang, &sn, &cs);

    float* p = buf + ((size_t)(s * NH + h) * HD) + i;
    float x1 = p[0];
    float x2 = p[64];
    p[0]  = x1 * cs - x2 * sn;
    p[64] = x2 * cs + x1 * sn;
}

// ---------------------------------------------------------------------------
// Flash attention: block = (head, q-tile of 64). 256 threads.
// O accumulators in registers (4 rows x 8 cols per thread),
// Q/K/V tiles + score tile in dynamic smem.
// ---------------------------------------------------------------------------
#define QSTR 132   // padded row stride for Q/K/V tiles (floats, 16B aligned)
#define SSTR 65    // padded row stride for score tile

#define FLASH_SMEM_FLOATS (3 * 64 * QSTR + 64 * SSTR + 64 + 64)
#define FLASH_SMEM_BYTES  (FLASH_SMEM_FLOATS * 4)

__global__ void __launch_bounds__(256)
flash_kernel(const float* __restrict__ cache_k,
             const float* __restrict__ cache_v)
{
    extern __shared__ float fsm[];
    float* Qs = fsm;
    float* Ks = Qs + 64 * QSTR;
    float* Vs = Ks + 64 * QSTR;
    float* Ss = Vs + 64 * QSTR;
    float* salpha = Ss + 64 * SSTR;   // per-row alpha this tile
    float* srow   = salpha + 64;      // per-row 1/l at the end

    const int h  = blockIdx.x;
    const int qt = blockIdx.y;
    const int tid = threadIdx.x;
    const int tx = tid & 15;
    const int ty = tid >> 4;

    // Load Q tile [64 x 128]
#pragma unroll
    for (int it = 0; it < 8; it++) {
        int idx = tid + it * 256;
        int r = idx >> 5;
        int c4 = (idx & 31) << 2;
        float4 v = *(const float4*)(g_q + (size_t)(qt * 64 + r) * DM + h * HD + c4);
        *(float4*)&Qs[r * QSTR + c4] = v;
    }

    float o[4][8];
#pragma unroll
    for (int i = 0; i < 4; i++)
#pragma unroll
        for (int j = 0; j < 8; j++) o[i][j] = 0.f;

    float m_r = -1e30f;  // valid for tid < 64
    float l_r = 0.f;

    const int ntiles = 33 + qt;  // keys visible: 2048 + (qt+1)*64
    for (int kt = 0; kt < ntiles; kt++) {
        __syncthreads();  // protect Ks/Vs/Ss from previous iteration readers

        // Load K,V tile [64 x 128] (from cache or new K/V)
        const int t0 = kt * 64;
#pragma unroll
        for (int it = 0; it < 8; it++) {
            int idx = tid + it * 256;
            int r = idx >> 5;
            int c4 = (idx & 31) << 2;
            int t = t0 + r;
            const float* ksrc;
            const float* vsrc;
            if (t < CACHE) {
                size_t off = ((size_t)t * NH + h) * HD + c4;
                ksrc = cache_k + off;
                vsrc = cache_v + off;
            } else {
                size_t off = (size_t)(t - CACHE) * DM + h * HD + c4;
                ksrc = g_k + off;
                vsrc = g_v + off;
            }
            *(float4*)&Ks[r * QSTR + c4] = *(const float4*)ksrc;
            *(float4*)&Vs[r * QSTR + c4] = *(const float4*)vsrc;
        }
        __syncthreads();

        // S = Q K^T * scale (64x64); thread computes 4 rows x 4 cols
        float sc[4][4];
#pragma unroll
        for (int i = 0; i < 4; i++)
#pragma unroll
            for (int j = 0; j < 4; j++) sc[i][j] = 0.f;

#pragma unroll 4
        for (int k = 0; k < HD; k += 4) {
            float4 a0 = *(const float4*)&Qs[(ty * 4 + 0) * QSTR + k];
            float4 a1 = *(const float4*)&Qs[(ty * 4 + 1) * QSTR + k];
            float4 a2 = *(const float4*)&Qs[(ty * 4 + 2) * QSTR + k];
            float4 a3 = *(const float4*)&Qs[(ty * 4 + 3) * QSTR + k];
            float4 b0 = *(const float4*)&Ks[(tx +  0) * QSTR + k];
            float4 b1 = *(const float4*)&Ks[(tx + 16) * QSTR + k];
            float4 b2 = *(const float4*)&Ks[(tx + 32) * QSTR + k];
            float4 b3 = *(const float4*)&Ks[(tx + 48) * QSTR + k];
#define DOT4(acc, A, B) acc = fmaf(A.x, B.x, fmaf(A.y, B.y, fmaf(A.z, B.z, fmaf(A.w, B.w, acc))))
            DOT4(sc[0][0], a0, b0); DOT4(sc[0][1], a0, b1); DOT4(sc[0][2], a0, b2); DOT4(sc[0][3], a0, b3);
            DOT4(sc[1][0], a1, b0); DOT4(sc[1][1], a1, b1); DOT4(sc[1][2], a1, b2); DOT4(sc[1][3], a1, b3);
            DOT4(sc[2][0], a2, b0); DOT4(sc[2][1], a2, b1); DOT4(sc[2][2], a2, b2); DOT4(sc[2][3], a2, b3);
            DOT4(sc[3][0], a3, b0); DOT4(sc[3][1], a3, b1); DOT4(sc[3][2], a3, b2); DOT4(sc[3][3], a3, b3);
#undef DOT4
        }

        const bool diag = (kt == ntiles - 1);
        const float scale = 0.08838834764831845f;  // 1/sqrt(128)
#pragma unroll
        for (int i = 0; i < 4; i++) {
            int r = ty * 4 + i;
#pragma unroll
            for (int j = 0; j < 4; j++) {
                int cc = tx + j * 16;
                float val = sc[i][j] * scale;
                if (diag && cc > r) val = -1e30f;
                Ss[r * SSTR + cc] = val;
            }
        }
        __syncthreads();

        // Online softmax: thread r (< 64) owns row r
        if (tid < 64) {
            float mx0 = m_r, mx1 = -1e30f, mx2 = -1e30f, mx3 = -1e30f;
            const float* srw = &Ss[tid * SSTR];
#pragma unroll
            for (int j = 0; j < 64; j += 4) {
                mx0 = fmaxf(mx0, srw[j + 0]);
                mx1 = fmaxf(mx1, srw[j + 1]);
                mx2 = fmaxf(mx2, srw[j + 2]);
                mx3 = fmaxf(mx3, srw[j + 3]);
            }
            float mx = fmaxf(fmaxf(mx0, mx1), fmaxf(mx2, mx3));
            float alpha = __expf(m_r - mx);
            float s0 = 0.f, s1 = 0.f, s2 = 0.f, s3 = 0.f;
            float* swr = &Ss[tid * SSTR];
#pragma unroll
            for (int j = 0; j < 64; j += 4) {
                float p0 = __expf(swr[j + 0] - mx);
                float p1 = __expf(swr[j + 1] - mx);
                float p2 = __expf(swr[j + 2] - mx);
                float p3 = __expf(swr[j + 3] - mx);
                swr[j + 0] = p0; swr[j + 1] = p1; swr[j + 2] = p2; swr[j + 3] = p3;
                s0 += p0; s1 += p1; s2 += p2; s3 += p3;
            }
            l_r = l_r * alpha + (s0 + s1) + (s2 + s3);
            m_r = mx;
            salpha[tid] = alpha;
        }
        __syncthreads();

        // Rescale O and accumulate O += P * V
#pragma unroll
        for (int i = 0; i < 4; i++) {
            float al = salpha[ty * 4 + i];
#pragma unroll
            for (int j = 0; j < 8; j++) o[i][j] *= al;
        }
#pragma unroll 4
        for (int kk = 0; kk < 64; kk++) {
            float4 v0 = *(const float4*)&Vs[kk * QSTR + tx * 8];
            float4 v1 = *(const float4*)&Vs[kk * QSTR + tx * 8 + 4];
            float b[8] = {v0.x, v0.y, v0.z, v0.w, v1.x, v1.y, v1.z, v1.w};
#pragma unroll
            for (int i = 0; i < 4; i++) {
                float a = Ss[(ty * 4 + i) * SSTR + kk];
#pragma unroll
                for (int j = 0; j < 8; j++)
                    o[i][j] = fmaf(a, b[j], o[i][j]);
            }
        }
    }

    __syncthreads();
    if (tid < 64) srow[tid] = 1.f / l_r;
    __syncthreads();

#pragma unroll
    for (int i = 0; i < 4; i++) {
        int r = ty * 4 + i;
        float inv = srow[r];
        size_t base = (size_t)(qt * 64 + r) * DM + h * HD + tx * 8;
        *(float4*)(g_at + base) =
            make_float4(o[i][0] * inv, o[i][1] * inv, o[i][2] * inv, o[i][3] * inv);
        *(float4*)(g_at + base + 4) =
            make_float4(o[i][4] * inv, o[i][5] * inv, o[i][6] * inv, o[i][7] * inv);
    }
}

// ---------------------------------------------------------------------------
// Launch
// ---------------------------------------------------------------------------
extern "C" void kernel_launch(void* const* d_in, const int* in_sizes, int n_in,
                              void* d_out, int out_size)
{
    (void)in_sizes; (void)n_in; (void)out_size;
    const float* xs      = (const float*)d_in[0];
    const float* cache_k = (const float*)d_in[1];
    const float* cache_v = (const float*)d_in[2];
    const float* norm_w  = (const float*)d_in[3];
    const float* wq      = (const float*)d_in[4];
    const float* wk      = (const float*)d_in[5];
    const float* wv      = (const float*)d_in[6];
    const float* wo      = (const float*)d_in[7];
    float* out = (float*)d_out;

    float *p_xn, *p_q, *p_k, *p_v, *p_at;
    cudaGetSymbolAddress((void**)&p_xn, g_xn);
    cudaGetSymbolAddress((void**)&p_q,  g_q);
    cudaGetSymbolAddress((void**)&p_k,  g_k);
    cudaGetSymbolAddress((void**)&p_v,  g_v);
    cudaGetSymbolAddress((void**)&p_at, g_at);

    // 1) RMSNorm
    rmsnorm_kernel<<<S_LEN, 256>>>(xs, norm_w);

    // 2) QKV projections: [1024,4096] @ [4096,4096]^T
    dim3 gg(DM / 128, S_LEN / 128);  // (32, 8)
    sgemm_nt<<<gg, 256>>>(p_xn, wq, p_q, DM, DM);
    sgemm_nt<<<gg, 256>>>(p_xn, wk, p_k, DM, DM);
    sgemm_nt<<<gg, 256>>>(p_xn, wv, p_v, DM, DM);

    // 3) RoPE on q and new k (offset = CACHE)
    const int rope_threads = S_LEN * NH * 64;
    rope_kernel<<<rope_threads / 256, 256>>>(p_q);
    rope_kernel<<<rope_threads / 256, 256>>>(p_k);

    // 4) Flash attention over [cache | new] keys/values
    cudaFuncSetAttribute(flash_kernel,
                         cudaFuncAttributeMaxDynamicSharedMemorySize,
                         FLASH_SMEM_BYTES);
    flash_kernel<<<dim3(NH, S_LEN / 64), 256, FLASH_SMEM_BYTES>>>(cache_k, cache_v);

    // 5) Output projection -> d_out
    sgemm_nt<<<gg, 256>>>(p_at, wo, out, DM, DM);
}

// round 2
// speedup vs baseline: 1.5932x; 1.5932x over previous
#include <cuda_runtime.h>
#include <math.h>
#include <stdint.h>

// Problem constants (fixed shapes for this problem instance)
#define S_LEN  1024
#define DM     4096
#define NH     32
#define HD     128
#define CACHE  2048

// Scratch (device globals: allocation-free rule)
__device__ float g_xn[S_LEN * DM];
__device__ float g_q [S_LEN * DM];
__device__ float g_k [S_LEN * DM];
__device__ float g_v [S_LEN * DM];
__device__ float g_at[S_LEN * DM];

// ---------------------------------------------------------------------------
// RMSNorm: one block per row (4096 elems), 256 threads
// ---------------------------------------------------------------------------
__global__ void rmsnorm_kernel(const float* __restrict__ xs,
                               const float* __restrict__ w)
{
    const int row = blockIdx.x;
    const int tid = threadIdx.x;
    const float* x = xs + (size_t)row * DM;
    float* y = g_xn + (size_t)row * DM;

    float ss = 0.f;
#pragma unroll
    for (int i = 0; i < 4; i++) {
        float4 v = *(const float4*)(x + (i * 256 + tid) * 4);
        ss += v.x * v.x + v.y * v.y + v.z * v.z + v.w * v.w;
    }
#pragma unroll
    for (int off = 16; off; off >>= 1)
        ss += __shfl_xor_sync(0xffffffffu, ss, off);

    __shared__ float red[8];
    __shared__ float s_inv;
    if ((tid & 31) == 0) red[tid >> 5] = ss;
    __syncthreads();
    if (tid == 0) {
        float t = 0.f;
#pragma unroll
        for (int i = 0; i < 8; i++) t += red[i];
        s_inv = rsqrtf(t / (float)DM + 1e-6f);
    }
    __syncthreads();
    const float inv = s_inv;
#pragma unroll
    for (int i = 0; i < 4; i++) {
        int base = (i * 256 + tid) * 4;
        float4 v = *(const float4*)(x + base);
        float4 g = *(const float4*)(w + base);
        v.x = v.x * inv * g.x;
        v.y = v.y * inv * g.y;
        v.z = v.z * inv * g.z;
        v.w = v.w * inv * g.w;
        *(float4*)(y + base) = v;
    }
}

// ---------------------------------------------------------------------------
// TF32 tensor-core GEMM (NT): C[M,N] = A[M,K] * B[N,K]^T, row-major,
// K contiguous. Tile 128x128x16, 256 threads (8 warps, each 64x32),
// mma.sync.m16n8k8.tf32, double-buffered smem, fp32 accumulate.
// ---------------------------------------------------------------------------
#define TSTR 136   // smem row stride in 32-bit words; 136 % 32 == 8 -> frag reads conflict-free

__device__ __forceinline__ uint32_t f2tf32(float x) {
    uint32_t r;
    asm("cvt.rna.tf32.f32 %0, %1;" : "=r"(r) : "f"(x));
    return r;
}

__device__ __forceinline__ void mma_tf32(float c[4], const uint32_t a[4], const uint32_t b[2]) {
    asm volatile(
        "mma.sync.aligned.m16n8k8.row.col.f32.tf32.tf32.f32 "
        "{%0,%1,%2,%3}, {%4,%5,%6,%7}, {%8,%9}, {%0,%1,%2,%3};"
        : "+f"(c[0]), "+f"(c[1]), "+f"(c[2]), "+f"(c[3])
        : "r"(a[0]), "r"(a[1]), "r"(a[2]), "r"(a[3]), "r"(b[0]), "r"(b[1]));
}

__global__ void __launch_bounds__(256, 2)
sgemm_tf32(const float* __restrict__ A, const float* __restrict__ B,
           float* __restrict__ C, int N, int K)
{
    __shared__ uint32_t As[2][16][TSTR];
    __shared__ uint32_t Bs[2][16][TSTR];

    const int tid  = threadIdx.x;
    const int lane = tid & 31;
    const int warp = tid >> 5;
    const int g    = lane >> 2;   // groupID (row within mma frag)
    const int tig  = lane & 3;    // thread-in-group

    const int wm = warp >> 2;     // 0..1 -> 64-row slab
    const int wn = warp & 3;      // 0..3 -> 32-col slab
    const int m_base = wm * 64;
    const int n_base = wn * 32;

    // Staging: thread -> (row, kcol pair)
    const int ldr = tid >> 1;            // 0..127
    const int ldc = (tid & 1) * 8;       // 0 or 8
    const float* Ag = A + (size_t)(blockIdx.y * 128 + ldr) * K + ldc;
    const float* Bg = B + (size_t)(blockIdx.x * 128 + ldr) * K + ldc;

    float c[4][4][4];
#pragma unroll
    for (int mt = 0; mt < 4; mt++)
#pragma unroll
        for (int nt = 0; nt < 4; nt++)
#pragma unroll
            for (int i = 0; i < 4; i++) c[mt][nt][i] = 0.f;

    // Preload tile 0 into buffer 0
    {
        float4 a0 = *(const float4*)(Ag + 0);
        float4 a1 = *(const float4*)(Ag + 4);
        float4 b0 = *(const float4*)(Bg + 0);
        float4 b1 = *(const float4*)(Bg + 4);
        As[0][ldc + 0][ldr] = f2tf32(a0.x); As[0][ldc + 1][ldr] = f2tf32(a0.y);
        As[0][ldc + 2][ldr] = f2tf32(a0.z); As[0][ldc + 3][ldr] = f2tf32(a0.w);
        As[0][ldc + 4][ldr] = f2tf32(a1.x); As[0][ldc + 5][ldr] = f2tf32(a1.y);
        As[0][ldc + 6][ldr] = f2tf32(a1.z); As[0][ldc + 7][ldr] = f2tf32(a1.w);
        Bs[0][ldc + 0][ldr] = f2tf32(b0.x); Bs[0][ldc + 1][ldr] = f2tf32(b0.y);
        Bs[0][ldc + 2][ldr] = f2tf32(b0.z); Bs[0][ldc + 3][ldr] = f2tf32(b0.w);
        Bs[0][ldc + 4][ldr] = f2tf32(b1.x); Bs[0][ldc + 5][ldr] = f2tf32(b1.y);
        Bs[0][ldc + 6][ldr] = f2tf32(b1.z); Bs[0][ldc + 7][ldr] = f2tf32(b1.w);
    }
    __syncthreads();

    const int KT = K >> 4;   // number of 16-wide k tiles
    int p = 0;
    for (int kt = 0; kt < KT; kt++) {
        // Prefetch next tile's global data into registers
        float4 pa0, pa1, pb0, pb1;
        const bool has_next = (kt + 1 < KT);
        if (has_next) {
            const int k0 = (kt + 1) << 4;
            pa0 = *(const float4*)(Ag + k0 + 0);
            pa1 = *(const float4*)(Ag + k0 + 4);
            pb0 = *(const float4*)(Bg + k0 + 0);
            pb1 = *(const float4*)(Bg + k0 + 4);
        }

        // Compute on current buffer
#pragma unroll
        for (int kk = 0; kk < 2; kk++) {
            const int ks = kk * 8;
            uint32_t af[4][4];
            uint32_t bf[4][2];
#pragma unroll
            for (int mt = 0; mt < 4; mt++) {
                const int m0 = m_base + mt * 16 + g;
                af[mt][0] = As[p][ks + tig    ][m0];
                af[mt][1] = As[p][ks + tig    ][m0 + 8];
                af[mt][2] = As[p][ks + tig + 4][m0];
                af[mt][3] = As[p][ks + tig + 4][m0 + 8];
            }
#pragma unroll
            for (int nt = 0; nt < 4; nt++) {
                const int n0 = n_base + nt * 8 + g;
                bf[nt][0] = Bs[p][ks + tig    ][n0];
                bf[nt][1] = Bs[p][ks + tig + 4][n0];
            }
#pragma unroll
            for (int mt = 0; mt < 4; mt++)
#pragma unroll
                for (int nt = 0; nt < 4; nt++)
                    mma_tf32(c[mt][nt], af[mt], bf[nt]);
        }

        // Stage prefetched data into the other buffer
        if (has_next) {
            const int q = p ^ 1;
            As[q][ldc + 0][ldr] = f2tf32(pa0.x); As[q][ldc + 1][ldr] = f2tf32(pa0.y);
            As[q][ldc + 2][ldr] = f2tf32(pa0.z); As[q][ldc + 3][ldr] = f2tf32(pa0.w);
            As[q][ldc + 4][ldr] = f2tf32(pa1.x); As[q][ldc + 5][ldr] = f2tf32(pa1.y);
            As[q][ldc + 6][ldr] = f2tf32(pa1.z); As[q][ldc + 7][ldr] = f2tf32(pa1.w);
            Bs[q][ldc + 0][ldr] = f2tf32(pb0.x); Bs[q][ldc + 1][ldr] = f2tf32(pb0.y);
            Bs[q][ldc + 2][ldr] = f2tf32(pb0.z); Bs[q][ldc + 3][ldr] = f2tf32(pb0.w);
            Bs[q][ldc + 4][ldr] = f2tf32(pb1.x); Bs[q][ldc + 5][ldr] = f2tf32(pb1.y);
            Bs[q][ldc + 6][ldr] = f2tf32(pb1.z); Bs[q][ldc + 7][ldr] = f2tf32(pb1.w);
        }
        __syncthreads();
        p ^= 1;
    }

    // Epilogue: c layout — c0:(g,2t) c1:(g,2t+1) c2:(g+8,2t) c3:(g+8,2t+1)
    const int crow = blockIdx.y * 128 + m_base + g;
    const int ccol = blockIdx.x * 128 + n_base + 2 * tig;
#pragma unroll
    for (int mt = 0; mt < 4; mt++) {
#pragma unroll
        for (int nt = 0; nt < 4; nt++) {
            const int row = crow + mt * 16;
            const int col = ccol + nt * 8;
            *(float2*)(C + (size_t)row * N + col) =
                make_float2(c[mt][nt][0], c[mt][nt][1]);
            *(float2*)(C + (size_t)(row + 8) * N + col) =
                make_float2(c[mt][nt][2], c[mt][nt][3]);
        }
    }
}

// ---------------------------------------------------------------------------
// RoPE (in-place) on a [S, NH, HD] fp32 buffer, position offset = CACHE
// ---------------------------------------------------------------------------
__global__ void rope_kernel(float* __restrict__ buf)
{
    int idx = blockIdx.x * blockDim.x + threadIdx.x;  // S*NH*64 threads
    int i = idx & 63;
    int h = (idx >> 6) & (NH - 1);
    int s = idx >> 11;

    float pos = (float)(s + CACHE);
    float inv_freq = exp2f(-(float)i * (13.287712379549449f / 64.f));
    float ang = pos * inv_freq;
    float sn, cs;
    sincosf(ang, &sn, &cs);

    float* p = buf + ((size_t)(s * NH + h) * HD) + i;
    float x1 = p[0];
    float x2 = p[64];
    p[0]  = x1 * cs - x2 * sn;
    p[64] = x2 * cs + x1 * sn;
}

// ---------------------------------------------------------------------------
// Flash attention: block = (head, q-tile of 64). 256 threads.
// ---------------------------------------------------------------------------
#define QSTR 132
#define SSTR 65

#define FLASH_SMEM_FLOATS (3 * 64 * QSTR + 64 * SSTR + 64 + 64)
#define FLASH_SMEM_BYTES  (FLASH_SMEM_FLOATS * 4)

__global__ void __launch_bounds__(256)
flash_kernel(const float* __restrict__ cache_k,
             const float* __restrict__ cache_v)
{
    extern __shared__ float fsm[];
    float* Qs = fsm;
    float* Ks = Qs + 64 * QSTR;
    float* Vs = Ks + 64 * QSTR;
    float* Ss = Vs + 64 * QSTR;
    float* salpha = Ss + 64 * SSTR;
    float* srow   = salpha + 64;

    const int h  = blockIdx.x;
    const int qt = blockIdx.y;
    const int tid = threadIdx.x;
    const int tx = tid & 15;
    const int ty = tid >> 4;

#pragma unroll
    for (int it = 0; it < 8; it++) {
        int idx = tid + it * 256;
        int r = idx >> 5;
        int c4 = (idx & 31) << 2;
        float4 v = *(const float4*)(g_q + (size_t)(qt * 64 + r) * DM + h * HD + c4);
        *(float4*)&Qs[r * QSTR + c4] = v;
    }

    float o[4][8];
#pragma unroll
    for (int i = 0; i < 4; i++)
#pragma unroll
        for (int j = 0; j < 8; j++) o[i][j] = 0.f;

    float m_r = -1e30f;
    float l_r = 0.f;

    const int ntiles = 33 + qt;
    for (int kt = 0; kt < ntiles; kt++) {
        __syncthreads();

        const int t0 = kt * 64;
#pragma unroll
        for (int it = 0; it < 8; it++) {
            int idx = tid + it * 256;
            int r = idx >> 5;
            int c4 = (idx & 31) << 2;
            int t = t0 + r;
            const float* ksrc;
            const float* vsrc;
            if (t < CACHE) {
                size_t off = ((size_t)t * NH + h) * HD + c4;
                ksrc = cache_k + off;
                vsrc = cache_v + off;
            } else {
                size_t off = (size_t)(t - CACHE) * DM + h * HD + c4;
                ksrc = g_k + off;
                vsrc = g_v + off;
            }
            *(float4*)&Ks[r * QSTR + c4] = *(const float4*)ksrc;
            *(float4*)&Vs[r * QSTR + c4] = *(const float4*)vsrc;
        }
        __syncthreads();

        float sc[4][4];
#pragma unroll
        for (int i = 0; i < 4; i++)
#pragma unroll
            for (int j = 0; j < 4; j++) sc[i][j] = 0.f;

#pragma unroll 4
        for (int k = 0; k < HD; k += 4) {
            float4 a0 = *(const float4*)&Qs[(ty * 4 + 0) * QSTR + k];
            float4 a1 = *(const float4*)&Qs[(ty * 4 + 1) * QSTR + k];
            float4 a2 = *(const float4*)&Qs[(ty * 4 + 2) * QSTR + k];
            float4 a3 = *(const float4*)&Qs[(ty * 4 + 3) * QSTR + k];
            float4 b0 = *(const float4*)&Ks[(tx +  0) * QSTR + k];
            float4 b1 = *(const float4*)&Ks[(tx + 16) * QSTR + k];
            float4 b2 = *(const float4*)&Ks[(tx + 32) * QSTR + k];
            float4 b3 = *(const float4*)&Ks[(tx + 48) * QSTR + k];
#define DOT4(acc, A, B) acc = fmaf(A.x, B.x, fmaf(A.y, B.y, fmaf(A.z, B.z, fmaf(A.w, B.w, acc))))
            DOT4(sc[0][0], a0, b0); DOT4(sc[0][1], a0, b1); DOT4(sc[0][2], a0, b2); DOT4(sc[0][3], a0, b3);
            DOT4(sc[1][0], a1, b0); DOT4(sc[1][1], a1, b1); DOT4(sc[1][2], a1, b2); DOT4(sc[1][3], a1, b3);
            DOT4(sc[2][0], a2, b0); DOT4(sc[2][1], a2, b1); DOT4(sc[2][2], a2, b2); DOT4(sc[2][3], a2, b3);
            DOT4(sc[3][0], a3, b0); DOT4(sc[3][1], a3, b1); DOT4(sc[3][2], a3, b2); DOT4(sc[3][3], a3, b3);
#undef DOT4
        }

        const bool diag = (kt == ntiles - 1);
        const float scale = 0.08838834764831845f;
#pragma unroll
        for (int i = 0; i < 4; i++) {
            int r = ty * 4 + i;
#pragma unroll
            for (int j = 0; j < 4; j++) {
                int cc = tx + j * 16;
                float val = sc[i][j] * scale;
                if (diag && cc > r) val = -1e30f;
                Ss[r * SSTR + cc] = val;
            }
        }
        __syncthreads();

        if (tid < 64) {
            float mx0 = m_r, mx1 = -1e30f, mx2 = -1e30f, mx3 = -1e30f;
            const float* srw = &Ss[tid * SSTR];
#pragma unroll
            for (int j = 0; j < 64; j += 4) {
                mx0 = fmaxf(mx0, srw[j + 0]);
                mx1 = fmaxf(mx1, srw[j + 1]);
                mx2 = fmaxf(mx2, srw[j + 2]);
                mx3 = fmaxf(mx3, srw[j + 3]);
            }
            float mx = fmaxf(fmaxf(mx0, mx1), fmaxf(mx2, mx3));
            float alpha = __expf(m_r - mx);
            float s0 = 0.f, s1 = 0.f, s2 = 0.f, s3 = 0.f;
            float* swr = &Ss[tid * SSTR];
#pragma unroll
            for (int j = 0; j < 64; j += 4) {
                float p0 = __expf(swr[j + 0] - mx);
                float p1 = __expf(swr[j + 1] - mx);
                float p2 = __expf(swr[j + 2] - mx);
                float p3 = __expf(swr[j + 3] - mx);
                swr[j + 0] = p0; swr[j + 1] = p1; swr[j + 2] = p2; swr[j + 3] = p3;
                s0 += p0; s1 += p1; s2 += p2; s3 += p3;
            }
            l_r = l_r * alpha + (s0 + s1) + (s2 + s3);
            m_r = mx;
            salpha[tid] = alpha;
        }
        __syncthreads();

#pragma unroll
        for (int i = 0; i < 4; i++) {
            float al = salpha[ty * 4 + i];
#pragma unroll
            for (int j = 0; j < 8; j++) o[i][j] *= al;
        }
#pragma unroll 4
        for (int kk = 0; kk < 64; kk++) {
            float4 v0 = *(const float4*)&Vs[kk * QSTR + tx * 8];
            float4 v1 = *(const float4*)&Vs[kk * QSTR + tx * 8 + 4];
            float b[8] = {v0.x, v0.y, v0.z, v0.w, v1.x, v1.y, v1.z, v1.w};
#pragma unroll
            for (int i = 0; i < 4; i++) {
                float a = Ss[(ty * 4 + i) * SSTR + kk];
#pragma unroll
                for (int j = 0; j < 8; j++)
                    o[i][j] = fmaf(a, b[j], o[i][j]);
            }
        }
    }

    __syncthreads();
    if (tid < 64) srow[tid] = 1.f / l_r;
    __syncthreads();

#pragma unroll
    for (int i = 0; i < 4; i++) {
        int r = ty * 4 + i;
        float inv = srow[r];
        size_t base = (size_t)(qt * 64 + r) * DM + h * HD + tx * 8;
        *(float4*)(g_at + base) =
            make_float4(o[i][0] * inv, o[i][1] * inv, o[i][2] * inv, o[i][3] * inv);
        *(float4*)(g_at + base + 4) =
            make_float4(o[i][4] * inv, o[i][5] * inv, o[i][6] * inv, o[i][7] * inv);
    }
}

// ---------------------------------------------------------------------------
// Launch
// ---------------------------------------------------------------------------
extern "C" void kernel_launch(void* const* d_in, const int* in_sizes, int n_in,
                              void* d_out, int out_size)
{
    (void)in_sizes; (void)n_in; (void)out_size;
    const float* xs      = (const float*)d_in[0];
    const float* cache_k = (const float*)d_in[1];
    const float* cache_v = (const float*)d_in[2];
    const float* norm_w  = (const float*)d_in[3];
    const float* wq      = (const float*)d_in[4];
    const float* wk      = (const float*)d_in[5];
    const float* wv      = (const float*)d_in[6];
    const float* wo      = (const float*)d_in[7];
    float* out = (float*)d_out;

    float *p_xn, *p_q, *p_k, *p_v, *p_at;
    cudaGetSymbolAddress((void**)&p_xn, g_xn);
    cudaGetSymbolAddress((void**)&p_q,  g_q);
    cudaGetSymbolAddress((void**)&p_k,  g_k);
    cudaGetSymbolAddress((void**)&p_v,  g_v);
    cudaGetSymbolAddress((void**)&p_at, g_at);

    // 1) RMSNorm
    rmsnorm_kernel<<<S_LEN, 256>>>(xs, norm_w);

    // 2) QKV projections: [1024,4096] @ [4096,4096]^T (tf32 tensor cores)
    dim3 gg(DM / 128, S_LEN / 128);  // (32, 8)
    sgemm_tf32<<<gg, 256>>>(p_xn, wq, p_q, DM, DM);
    sgemm_tf32<<<gg, 256>>>(p_xn, wk, p_k, DM, DM);
    sgemm_tf32<<<gg, 256>>>(p_xn, wv, p_v, DM, DM);

    // 3) RoPE on q and new k (offset = CACHE)
    const int rope_threads = S_LEN * NH * 64;
    rope_kernel<<<rope_threads / 256, 256>>>(p_q);
    rope_kernel<<<rope_threads / 256, 256>>>(p_k);

    // 4) Flash attention over [cache | new] keys/values
    cudaFuncSetAttribute(flash_kernel,
                         cudaFuncAttributeMaxDynamicSharedMemorySize,
                         FLASH_SMEM_BYTES);
    flash_kernel<<<dim3(NH, S_LEN / 64), 256, FLASH_SMEM_BYTES>>>(cache_k, cache_v);

    // 5) Output projection -> d_out (tf32 tensor cores)
    sgemm_tf32<<<gg, 256>>>(p_at, wo, out, DM, DM);
}

// round 4
// speedup vs baseline: 2.9436x; 1.8476x over previous
#include <cuda_runtime.h>
#include <math.h>
#include <stdint.h>

// Problem constants (fixed shapes for this problem instance)
#define S_LEN  1024
#define DM     4096
#define NH     32
#define HD     128
#define CACHE  2048
#define TTOT   (CACHE + S_LEN)   // 3072 total kv positions

// Scratch (device globals: allocation-free rule)
__device__ float g_xn[S_LEN * DM];
__device__ float g_q [S_LEN * DM];
__device__ float g_k [S_LEN * DM];
__device__ float g_v [S_LEN * DM];
__device__ float g_at[S_LEN * DM];
__device__ float g_kc[(size_t)TTOT * DM];   // tf32-rounded unified K [T,H,HD]
__device__ float g_vc[(size_t)TTOT * DM];   // tf32-rounded unified V [T,H,HD]

// ---------------------------------------------------------------------------
// Common tensor-core helpers
// ---------------------------------------------------------------------------
__device__ __forceinline__ uint32_t f2tf32(float x) {
    uint32_t r;
    asm("cvt.rna.tf32.f32 %0, %1;" : "=r"(r) : "f"(x));
    return r;
}

__device__ __forceinline__ void mma_tf32(float c[4], const uint32_t a[4], const uint32_t b[2]) {
    asm volatile(
        "mma.sync.aligned.m16n8k8.row.col.f32.tf32.tf32.f32 "
        "{%0,%1,%2,%3}, {%4,%5,%6,%7}, {%8,%9}, {%0,%1,%2,%3};"
        : "+f"(c[0]), "+f"(c[1]), "+f"(c[2]), "+f"(c[3])
        : "r"(a[0]), "r"(a[1]), "r"(a[2]), "r"(a[3]), "r"(b[0]), "r"(b[1]));
}

__device__ __forceinline__ void cp16(uint32_t dst, const void* src) {
    asm volatile("cp.async.cg.shared.global [%0], [%1], 16;" :: "r"(dst), "l"(src));
}
#define CP_COMMIT()  asm volatile("cp.async.commit_group;")
#define CP_WAIT0()   asm volatile("cp.async.wait_group 0;")

// ---------------------------------------------------------------------------
// RMSNorm: one block per row (4096 elems), 256 threads
// ---------------------------------------------------------------------------
__global__ void rmsnorm_kernel(const float* __restrict__ xs,
                               const float* __restrict__ w)
{
    const int row = blockIdx.x;
    const int tid = threadIdx.x;
    const float* x = xs + (size_t)row * DM;
    float* y = g_xn + (size_t)row * DM;

    float ss = 0.f;
#pragma unroll
    for (int i = 0; i < 4; i++) {
        float4 v = *(const float4*)(x + (i * 256 + tid) * 4);
        ss += v.x * v.x + v.y * v.y + v.z * v.z + v.w * v.w;
    }
#pragma unroll
    for (int off = 16; off; off >>= 1)
        ss += __shfl_xor_sync(0xffffffffu, ss, off);

    __shared__ float red[8];
    __shared__ float s_inv;
    if ((tid & 31) == 0) red[tid >> 5] = ss;
    __syncthreads();
    if (tid == 0) {
        float t = 0.f;
#pragma unroll
        for (int i = 0; i < 8; i++) t += red[i];
        s_inv = rsqrtf(t / (float)DM + 1e-6f);
    }
    __syncthreads();
    const float inv = s_inv;
#pragma unroll
    for (int i = 0; i < 4; i++) {
        int base = (i * 256 + tid) * 4;
        float4 v = *(const float4*)(x + base);
        float4 g = *(const float4*)(w + base);
        v.x = v.x * inv * g.x;
        v.y = v.y * inv * g.y;
        v.z = v.z * inv * g.z;
        v.w = v.w * inv * g.w;
        *(float4*)(y + base) = v;
    }
}

// ---------------------------------------------------------------------------
// TF32 tensor-core GEMM (NT): C[M,N] = A[M,K] * B[N,K]^T
// ---------------------------------------------------------------------------
#define TSTR 136

__global__ void __launch_bounds__(256, 2)
sgemm_tf32(const float* __restrict__ A, const float* __restrict__ B,
           float* __restrict__ C, int N, int K)
{
    __shared__ uint32_t As[2][16][TSTR];
    __shared__ uint32_t Bs[2][16][TSTR];

    const int tid  = threadIdx.x;
    const int lane = tid & 31;
    const int warp = tid >> 5;
    const int g    = lane >> 2;
    const int tig  = lane & 3;

    const int wm = warp >> 2;
    const int wn = warp & 3;
    const int m_base = wm * 64;
    const int n_base = wn * 32;

    const int ldr = tid >> 1;
    const int ldc = (tid & 1) * 8;
    const float* Ag = A + (size_t)(blockIdx.y * 128 + ldr) * K + ldc;
    const float* Bg = B + (size_t)(blockIdx.x * 128 + ldr) * K + ldc;

    float c[4][4][4];
#pragma unroll
    for (int mt = 0; mt < 4; mt++)
#pragma unroll
        for (int nt = 0; nt < 4; nt++)
#pragma unroll
            for (int i = 0; i < 4; i++) c[mt][nt][i] = 0.f;

    {
        float4 a0 = *(const float4*)(Ag + 0);
        float4 a1 = *(const float4*)(Ag + 4);
        float4 b0 = *(const float4*)(Bg + 0);
        float4 b1 = *(const float4*)(Bg + 4);
        As[0][ldc + 0][ldr] = f2tf32(a0.x); As[0][ldc + 1][ldr] = f2tf32(a0.y);
        As[0][ldc + 2][ldr] = f2tf32(a0.z); As[0][ldc + 3][ldr] = f2tf32(a0.w);
        As[0][ldc + 4][ldr] = f2tf32(a1.x); As[0][ldc + 5][ldr] = f2tf32(a1.y);
        As[0][ldc + 6][ldr] = f2tf32(a1.z); As[0][ldc + 7][ldr] = f2tf32(a1.w);
        Bs[0][ldc + 0][ldr] = f2tf32(b0.x); Bs[0][ldc + 1][ldr] = f2tf32(b0.y);
        Bs[0][ldc + 2][ldr] = f2tf32(b0.z); Bs[0][ldc + 3][ldr] = f2tf32(b0.w);
        Bs[0][ldc + 4][ldr] = f2tf32(b1.x); Bs[0][ldc + 5][ldr] = f2tf32(b1.y);
        Bs[0][ldc + 6][ldr] = f2tf32(b1.z); Bs[0][ldc + 7][ldr] = f2tf32(b1.w);
    }
    __syncthreads();

    const int KT = K >> 4;
    int p = 0;
    for (int kt = 0; kt < KT; kt++) {
        float4 pa0, pa1, pb0, pb1;
        const bool has_next = (kt + 1 < KT);
        if (has_next) {
            const int k0 = (kt + 1) << 4;
            pa0 = *(const float4*)(Ag + k0 + 0);
            pa1 = *(const float4*)(Ag + k0 + 4);
            pb0 = *(const float4*)(Bg + k0 + 0);
            pb1 = *(const float4*)(Bg + k0 + 4);
        }

#pragma unroll
        for (int kk = 0; kk < 2; kk++) {
            const int ks = kk * 8;
            uint32_t af[4][4];
            uint32_t bf[4][2];
#pragma unroll
            for (int mt = 0; mt < 4; mt++) {
                const int m0 = m_base + mt * 16 + g;
                af[mt][0] = As[p][ks + tig    ][m0];
                af[mt][1] = As[p][ks + tig    ][m0 + 8];
                af[mt][2] = As[p][ks + tig + 4][m0];
                af[mt][3] = As[p][ks + tig + 4][m0 + 8];
            }
#pragma unroll
            for (int nt = 0; nt < 4; nt++) {
                const int n0 = n_base + nt * 8 + g;
                bf[nt][0] = Bs[p][ks + tig    ][n0];
                bf[nt][1] = Bs[p][ks + tig + 4][n0];
            }
#pragma unroll
            for (int mt = 0; mt < 4; mt++)
#pragma unroll
                for (int nt = 0; nt < 4; nt++)
                    mma_tf32(c[mt][nt], af[mt], bf[nt]);
        }

        if (has_next) {
            const int q = p ^ 1;
            As[q][ldc + 0][ldr] = f2tf32(pa0.x); As[q][ldc + 1][ldr] = f2tf32(pa0.y);
            As[q][ldc + 2][ldr] = f2tf32(pa0.z); As[q][ldc + 3][ldr] = f2tf32(pa0.w);
            As[q][ldc + 4][ldr] = f2tf32(pa1.x); As[q][ldc + 5][ldr] = f2tf32(pa1.y);
            As[q][ldc + 6][ldr] = f2tf32(pa1.z); As[q][ldc + 7][ldr] = f2tf32(pa1.w);
            Bs[q][ldc + 0][ldr] = f2tf32(pb0.x); Bs[q][ldc + 1][ldr] = f2tf32(pb0.y);
            Bs[q][ldc + 2][ldr] = f2tf32(pb0.z); Bs[q][ldc + 3][ldr] = f2tf32(pb0.w);
            Bs[q][ldc + 4][ldr] = f2tf32(pb1.x); Bs[q][ldc + 5][ldr] = f2tf32(pb1.y);
            Bs[q][ldc + 6][ldr] = f2tf32(pb1.z); Bs[q][ldc + 7][ldr] = f2tf32(pb1.w);
        }
        __syncthreads();
        p ^= 1;
    }

    const int crow = blockIdx.y * 128 + m_base + g;
    const int ccol = blockIdx.x * 128 + n_base + 2 * tig;
#pragma unroll
    for (int mt = 0; mt < 4; mt++) {
#pragma unroll
        for (int nt = 0; nt < 4; nt++) {
            const int row = crow + mt * 16;
            const int col = ccol + nt * 8;
            *(float2*)(C + (size_t)row * N + col) =
                make_float2(c[mt][nt][0], c[mt][nt][1]);
            *(float2*)(C + (size_t)(row + 8) * N + col) =
                make_float2(c[mt][nt][2], c[mt][nt][3]);
        }
    }
}

// ---------------------------------------------------------------------------
// RoPE (in-place) on a [S, NH, HD] fp32 buffer, position offset = CACHE
// ---------------------------------------------------------------------------
__global__ void rope_kernel(float* __restrict__ buf)
{
    int idx = blockIdx.x * blockDim.x + threadIdx.x;
    int i = idx & 63;
    int h = (idx >> 6) & (NH - 1);
    int s = idx >> 11;

    float pos = (float)(s + CACHE);
    float inv_freq = exp2f(-(float)i * (13.287712379549449f / 64.f));
    float ang = pos * inv_freq;
    float sn, cs;
    sincosf(ang, &sn, &cs);

    float* p = buf + ((size_t)(s * NH + h) * HD) + i;
    float x1 = p[0];
    float x2 = p[64];
    p[0]  = x1 * cs - x2 * sn;
    p[64] = x2 * cs + x1 * sn;
}

// ---------------------------------------------------------------------------
// Convert K/V (cache + new) into unified, RNA-rounded tf32 buffers [T,H,HD].
// Removes the tf32-truncation BIAS that broke round 3, and removes the
// cache/new branch from the flash load loop.
// ---------------------------------------------------------------------------
__global__ void convert_kv_kernel(const float* __restrict__ cache_k,
                                  const float* __restrict__ cache_v)
{
    const size_t i4 = (size_t)blockIdx.x * blockDim.x + threadIdx.x;
    const size_t elem = i4 * 4;
    const size_t t = elem / DM;
    const size_t rem = elem - t * DM;

    const float4* ks;
    const float4* vs;
    if (t < CACHE) {
        ks = (const float4*)(cache_k + elem);
        vs = (const float4*)(cache_v + elem);
    } else {
        size_t off = (t - CACHE) * DM + rem;
        ks = (const float4*)(g_k + off);
        vs = (const float4*)(g_v + off);
    }
    float4 k = *ks, v = *vs;
    uint4 ko, vo;
    ko.x = f2tf32(k.x); ko.y = f2tf32(k.y); ko.z = f2tf32(k.z); ko.w = f2tf32(k.w);
    vo.x = f2tf32(v.x); vo.y = f2tf32(v.y); vo.z = f2tf32(v.z); vo.w = f2tf32(v.w);
    *(uint4*)(g_kc + elem) = ko;
    *(uint4*)(g_vc + elem) = vo;
}

// ---------------------------------------------------------------------------
// Tensor-core flash attention (as round 3, loads from pre-rounded g_kc/g_vc)
// ---------------------------------------------------------------------------
#define KQSTR 132
#define VSTR  136
#define PSTR  68

#define QS_WORDS (64 * KQSTR)
#define KS_WORDS (64 * KQSTR)
#define VS_WORDS (64 * VSTR)
#define PS_WORDS (64 * PSTR)

#define FLASH_SMEM_WORDS (QS_WORDS + 2*KS_WORDS + 2*VS_WORDS + PS_WORDS + 192)
#define FLASH_SMEM_BYTES (FLASH_SMEM_WORDS * 4)

__global__ void __launch_bounds__(256, 1)
flash_tc_kernel()
{
    extern __shared__ uint32_t fsm[];
    uint32_t* Qs  = fsm;
    uint32_t* Ks0 = Qs  + QS_WORDS;
    uint32_t* Ks1 = Ks0 + KS_WORDS;
    uint32_t* Vs0 = Ks1 + KS_WORDS;
    uint32_t* Vs1 = Vs0 + VS_WORDS;
    uint32_t* Ps  = Vs1 + VS_WORDS;
    float* m_s    = (float*)(Ps + PS_WORDS);
    float* l_s    = m_s + 64;
    float* salpha = l_s + 64;
    float* PsF    = (float*)Ps;

    const int h  = blockIdx.x;
    const int qt = (S_LEN / 64 - 1) - blockIdx.y;  // long blocks first
    const int tid = threadIdx.x;
    const int lane = tid & 31;
    const int warp = tid >> 5;
    const int g    = lane >> 2;
    const int tig  = lane & 3;
    const int wr   = warp >> 1;
    const int wc   = warp & 1;
    const int m0   = wr * 16;

    const uint32_t ks0_a = (uint32_t)__cvta_generic_to_shared(Ks0);
    const uint32_t ks1_a = (uint32_t)__cvta_generic_to_shared(Ks1);
    const uint32_t vs0_a = (uint32_t)__cvta_generic_to_shared(Vs0);
    const uint32_t vs1_a = (uint32_t)__cvta_generic_to_shared(Vs1);

    // ---- Load Q tile (scaled, rna tf32) ----
    const float qscale = 0.08838834764831845f;  // 1/sqrt(128)
#pragma unroll
    for (int it = 0; it < 8; it++) {
        int idx = it * 256 + tid;
        int r = idx >> 5;
        int c = (idx & 31) << 2;
        float4 v = *(const float4*)(g_q + (size_t)(qt * 64 + r) * DM + h * HD + c);
        uint4 u;
        u.x = f2tf32(v.x * qscale);
        u.y = f2tf32(v.y * qscale);
        u.z = f2tf32(v.z * qscale);
        u.w = f2tf32(v.w * qscale);
        *(uint4*)&Qs[r * KQSTR + c] = u;
    }
    if (tid < 64) { m_s[tid] = -1e30f; l_s[tid] = 0.f; }

    // ---- issue K/V tile kt into buffer b (unified pre-rounded buffers) ----
    auto issue_kv = [&](int kt, int b) {
        const int t0 = kt * 64;
        const uint32_t ka = b ? ks1_a : ks0_a;
        const uint32_t va = b ? vs1_a : vs0_a;
#pragma unroll
        for (int it = 0; it < 8; it++) {
            int idx = it * 256 + tid;
            int r = idx >> 5;
            int c = (idx & 31) << 2;
            size_t off = (size_t)(t0 + r) * DM + h * HD + c;
            cp16(ka + (r * KQSTR + c) * 4, g_kc + off);
            cp16(va + (r * VSTR  + c) * 4, g_vc + off);
        }
        CP_COMMIT();
    };

    issue_kv(0, 0);

    float oacc[8][4];
#pragma unroll
    for (int nt = 0; nt < 8; nt++)
#pragma unroll
        for (int i = 0; i < 4; i++) oacc[nt][i] = 0.f;

    const int ntiles = 33 + qt;
    int p = 0;
    for (int kt = 0; kt < ntiles; kt++) {
        CP_WAIT0();
        __syncthreads();
        if (kt + 1 < ntiles) issue_kv(kt + 1, p ^ 1);

        const uint32_t* Kc = p ? Ks1 : Ks0;
        const uint32_t* Vc = p ? Vs1 : Vs0;

        // ---- S = Q K^T (warp tile 16x32) ----
        float sacc[4][4];
#pragma unroll
        for (int nt = 0; nt < 4; nt++)
#pragma unroll
            for (int i = 0; i < 4; i++) sacc[nt][i] = 0.f;

        const uint32_t* Qb = Qs + (m0 + g) * KQSTR;
        const uint32_t* Kb = Kc + (wc * 32 + g) * KQSTR;
#pragma unroll
        for (int ks = 0; ks < 16; ks++) {
            const int k0 = ks * 8;
            uint32_t a[4];
            a[0] = Qb[k0 + tig];
            a[1] = Qb[8 * KQSTR + k0 + tig];
            a[2] = Qb[k0 + tig + 4];
            a[3] = Qb[8 * KQSTR + k0 + tig + 4];
#pragma unroll
            for (int nt = 0; nt < 4; nt++) {
                uint32_t b[2];
                b[0] = Kb[nt * 8 * KQSTR + k0 + tig];
                b[1] = Kb[nt * 8 * KQSTR + k0 + tig + 4];
                mma_tf32(sacc[nt], a, b);
            }
        }

        // ---- write S (masked) to Ps as fp32 ----
        const bool diag = (kt == ntiles - 1);
        const int r0 = m0 + g, r1 = m0 + g + 8;
#pragma unroll
        for (int nt = 0; nt < 4; nt++) {
            int col = wc * 32 + nt * 8 + 2 * tig;
            float v0 = sacc[nt][0], v1 = sacc[nt][1];
            float v2 = sacc[nt][2], v3 = sacc[nt][3];
            if (diag) {
                if (col     > r0) v0 = -1e30f;
                if (col + 1 > r0) v1 = -1e30f;
                if (col     > r1) v2 = -1e30f;
                if (col + 1 > r1) v3 = -1e30f;
            }
            *(float2*)&PsF[r0 * PSTR + col] = make_float2(v0, v1);
            *(float2*)&PsF[r1 * PSTR + col] = make_float2(v2, v3);
        }
        __syncthreads();

        // ---- online softmax: 4 threads per row ----
        {
            const int row = tid >> 2;
            const int qd  = tid & 3;
            float* pr = PsF + row * PSTR + qd * 16;
            float4 x0 = *(float4*)(pr + 0);
            float4 x1 = *(float4*)(pr + 4);
            float4 x2 = *(float4*)(pr + 8);
            float4 x3 = *(float4*)(pr + 12);
            float mp = fmaxf(fmaxf(fmaxf(x0.x, x0.y), fmaxf(x0.z, x0.w)),
                             fmaxf(fmaxf(x1.x, x1.y), fmaxf(x1.z, x1.w)));
            mp = fmaxf(mp, fmaxf(fmaxf(fmaxf(x2.x, x2.y), fmaxf(x2.z, x2.w)),
                                 fmaxf(fmaxf(x3.x, x3.y), fmaxf(x3.z, x3.w))));
            mp = fmaxf(mp, __shfl_xor_sync(0xffffffffu, mp, 1));
            mp = fmaxf(mp, __shfl_xor_sync(0xffffffffu, mp, 2));
            const float mold = m_s[row];
            const float mx = fmaxf(mold, mp);
            float sum;
            {
                uint4 u;
                float s = 0.f;
                float p0, p1, p2, p3;
                p0 = __expf(x0.x - mx); p1 = __expf(x0.y - mx);
                p2 = __expf(x0.z - mx); p3 = __expf(x0.w - mx);
                s += (p0 + p1) + (p2 + p3);
                u.x = f2tf32(p0); u.y = f2tf32(p1); u.z = f2tf32(p2); u.w = f2tf32(p3);
                *(uint4*)(pr + 0) = u;
                p0 = __expf(x1.x - mx); p1 = __expf(x1.y - mx);
                p2 = __expf(x1.z - mx); p3 = __expf(x1.w - mx);
                s += (p0 + p1) + (p2 + p3);
                u.x = f2tf32(p0); u.y = f2tf32(p1); u.z = f2tf32(p2); u.w = f2tf32(p3);
                *(uint4*)(pr + 4) = u;
                p0 = __expf(x2.x - mx); p1 = __expf(x2.y - mx);
                p2 = __expf(x2.z - mx); p3 = __expf(x2.w - mx);
                s += (p0 + p1) + (p2 + p3);
                u.x = f2tf32(p0); u.y = f2tf32(p1); u.z = f2tf32(p2); u.w = f2tf32(p3);
                *(uint4*)(pr + 8) = u;
                p0 = __expf(x3.x - mx); p1 = __expf(x3.y - mx);
                p2 = __expf(x3.z - mx); p3 = __expf(x3.w - mx);
                s += (p0 + p1) + (p2 + p3);
                u.x = f2tf32(p0); u.y = f2tf32(p1); u.z = f2tf32(p2); u.w = f2tf32(p3);
                *(uint4*)(pr + 12) = u;
                sum = s;
            }
            sum += __shfl_xor_sync(0xffffffffu, sum, 1);
            sum += __shfl_xor_sync(0xffffffffu, sum, 2);
            __syncwarp();
            if (qd == 0) {
                float alpha = __expf(mold - mx);
                l_s[row] = l_s[row] * alpha + sum;
                m_s[row] = mx;
                salpha[row] = alpha;
            }
        }
        __syncthreads();

        // ---- rescale O, then O += P V (warp tile 16x64) ----
        {
            const float alo = salpha[m0 + g];
            const float ahi = salpha[m0 + g + 8];
#pragma unroll
            for (int nt = 0; nt < 8; nt++) {
                oacc[nt][0] *= alo; oacc[nt][1] *= alo;
                oacc[nt][2] *= ahi; oacc[nt][3] *= ahi;
            }
            const uint32_t* Pb = Ps + (m0 + g) * PSTR;
#pragma unroll
            for (int ks = 0; ks < 8; ks++) {
                const int k0 = ks * 8;
                uint32_t a[4];
                a[0] = Pb[k0 + tig];
                a[1] = Pb[8 * PSTR + k0 + tig];
                a[2] = Pb[k0 + tig + 4];
                a[3] = Pb[8 * PSTR + k0 + tig + 4];
                const uint32_t* V0 = Vc + (k0 + tig) * VSTR + wc * 64 + g;
                const uint32_t* V1 = V0 + 4 * VSTR;
#pragma unroll
                for (int nt = 0; nt < 8; nt++) {
                    uint32_t b[2];
                    b[0] = V0[nt * 8];
                    b[1] = V1[nt * 8];
                    mma_tf32(oacc[nt], a, b);
                }
            }
        }
        p ^= 1;
    }

    // ---- epilogue: O / l -> g_at ----
    __syncthreads();
    const float ilo = 1.f / l_s[m0 + g];
    const float ihi = 1.f / l_s[m0 + g + 8];
    const int grow = qt * 64 + m0 + g;
#pragma unroll
    for (int nt = 0; nt < 8; nt++) {
        const int col = h * HD + wc * 64 + nt * 8 + 2 * tig;
        *(float2*)(g_at + (size_t)grow * DM + col) =
            make_float2(oacc[nt][0] * ilo, oacc[nt][1] * ilo);
        *(float2*)(g_at + (size_t)(grow + 8) * DM + col) =
            make_float2(oacc[nt][2] * ihi, oacc[nt][3] * ihi);
    }
}

// ---------------------------------------------------------------------------
// Launch
// ---------------------------------------------------------------------------
extern "C" void kernel_launch(void* const* d_in, const int* in_sizes, int n_in,
                              void* d_out, int out_size)
{
    (void)in_sizes; (void)n_in; (void)out_size;
    const float* xs      = (const float*)d_in[0];
    const float* cache_k = (const float*)d_in[1];
    const float* cache_v = (const float*)d_in[2];
    const float* norm_w  = (const float*)d_in[3];
    const float* wq      = (const float*)d_in[4];
    const float* wk      = (const float*)d_in[5];
    const float* wv      = (const float*)d_in[6];
    const float* wo      = (const float*)d_in[7];
    float* out = (float*)d_out;

    float *p_xn, *p_q, *p_k, *p_v, *p_at;
    cudaGetSymbolAddress((void**)&p_xn, g_xn);
    cudaGetSymbolAddress((void**)&p_q,  g_q);
    cudaGetSymbolAddress((void**)&p_k,  g_k);
    cudaGetSymbolAddress((void**)&p_v,  g_v);
    cudaGetSymbolAddress((void**)&p_at, g_at);

    // 1) RMSNorm
    rmsnorm_kernel<<<S_LEN, 256>>>(xs, norm_w);

    // 2) QKV projections (tf32 tensor cores)
    dim3 gg(DM / 128, S_LEN / 128);
    sgemm_tf32<<<gg, 256>>>(p_xn, wq, p_q, DM, DM);
    sgemm_tf32<<<gg, 256>>>(p_xn, wk, p_k, DM, DM);
    sgemm_tf32<<<gg, 256>>>(p_xn, wv, p_v, DM, DM);

    // 3) RoPE on q and new k
    const int rope_threads = S_LEN * NH * 64;
    rope_kernel<<<rope_threads / 256, 256>>>(p_q);
    rope_kernel<<<rope_threads / 256, 256>>>(p_k);

    // 4) Unified + RNA-rounded K/V buffers (kills tf32 truncation bias)
    {
        const size_t n4 = (size_t)TTOT * DM / 4;
        convert_kv_kernel<<<(unsigned)(n4 / 256), 256>>>(cache_k, cache_v);
    }

    // 5) Tensor-core flash attention
    cudaFuncSetAttribute(flash_tc_kernel,
                         cudaFuncAttributeMaxDynamicSharedMemorySize,
                         FLASH_SMEM_BYTES);
    flash_tc_kernel<<<dim3(NH, S_LEN / 64), 256, FLASH_SMEM_BYTES>>>();

    // 6) Output projection -> d_out
    sgemm_tf32<<<gg, 256>>>(p_at, wo, out, DM, DM);
}

// round 5
// speedup vs baseline: 3.6007x; 1.2232x over previous
#include <cuda_runtime.h>
#include <math.h>
#include <stdint.h>

// Problem constants (fixed shapes for this problem instance)
#define S_LEN  1024
#define DM     4096
#define NH     32
#define HD     128
#define CACHE  2048
#define TTOT   (CACHE + S_LEN)   // 3072 total kv positions

// Scratch (device globals: allocation-free rule)
__device__ float g_xn[S_LEN * DM];
__device__ float g_q [S_LEN * DM];
__device__ float g_k [S_LEN * DM];
__device__ float g_v [S_LEN * DM];
__device__ float g_at[S_LEN * DM];
__device__ float g_kc[(size_t)TTOT * DM];   // tf32-rounded unified K [T,H,HD]
__device__ float g_vc[(size_t)TTOT * DM];   // tf32-rounded unified V [T,H,HD]
__device__ float g_wqc[(size_t)DM * DM];    // tf32-rounded weights
__device__ float g_wkc[(size_t)DM * DM];
__device__ float g_wvc[(size_t)DM * DM];
__device__ float g_woc[(size_t)DM * DM];

// ---------------------------------------------------------------------------
// Common tensor-core helpers
// ---------------------------------------------------------------------------
__device__ __forceinline__ uint32_t f2tf32(float x) {
    uint32_t r;
    asm("cvt.rna.tf32.f32 %0, %1;" : "=r"(r) : "f"(x));
    return r;
}

__device__ __forceinline__ void mma_tf32(float c[4], const uint32_t a[4], const uint32_t b[2]) {
    asm volatile(
        "mma.sync.aligned.m16n8k8.row.col.f32.tf32.tf32.f32 "
        "{%0,%1,%2,%3}, {%4,%5,%6,%7}, {%8,%9}, {%0,%1,%2,%3};"
        : "+f"(c[0]), "+f"(c[1]), "+f"(c[2]), "+f"(c[3])
        : "r"(a[0]), "r"(a[1]), "r"(a[2]), "r"(a[3]), "r"(b[0]), "r"(b[1]));
}

__device__ __forceinline__ void ldsm4(uint32_t r[4], uint32_t addr) {
    asm volatile("ldmatrix.sync.aligned.m8n8.x4.shared.b16 {%0,%1,%2,%3}, [%4];"
        : "=r"(r[0]), "=r"(r[1]), "=r"(r[2]), "=r"(r[3]) : "r"(addr));
}

__device__ __forceinline__ void cp16(uint32_t dst, const void* src) {
    asm volatile("cp.async.cg.shared.global [%0], [%1], 16;" :: "r"(dst), "l"(src));
}
#define CP_COMMIT()  asm volatile("cp.async.commit_group;")
#define CP_WAIT0()   asm volatile("cp.async.wait_group 0;")
#define CP_WAIT1()   asm volatile("cp.async.wait_group 1;")
#define CP_WAIT2()   asm volatile("cp.async.wait_group 2;")

// ---------------------------------------------------------------------------
// RMSNorm: one block per row (4096 elems), 256 threads.
// Output is RNA-rounded to tf32 (it is only ever consumed as a GEMM A input).
// ---------------------------------------------------------------------------
__global__ void rmsnorm_kernel(const float* __restrict__ xs,
                               const float* __restrict__ w)
{
    const int row = blockIdx.x;
    const int tid = threadIdx.x;
    const float* x = xs + (size_t)row * DM;
    float* y = g_xn + (size_t)row * DM;

    float ss = 0.f;
#pragma unroll
    for (int i = 0; i < 4; i++) {
        float4 v = *(const float4*)(x + (i * 256 + tid) * 4);
        ss += v.x * v.x + v.y * v.y + v.z * v.z + v.w * v.w;
    }
#pragma unroll
    for (int off = 16; off; off >>= 1)
        ss += __shfl_xor_sync(0xffffffffu, ss, off);

    __shared__ float red[8];
    __shared__ float s_inv;
    if ((tid & 31) == 0) red[tid >> 5] = ss;
    __syncthreads();
    if (tid == 0) {
        float t = 0.f;
#pragma unroll
        for (int i = 0; i < 8; i++) t += red[i];
        s_inv = rsqrtf(t / (float)DM + 1e-6f);
    }
    __syncthreads();
    const float inv = s_inv;
#pragma unroll
    for (int i = 0; i < 4; i++) {
        int base = (i * 256 + tid) * 4;
        float4 v = *(const float4*)(x + base);
        float4 g = *(const float4*)(w + base);
        uint4 u;
        u.x = f2tf32(v.x * inv * g.x);
        u.y = f2tf32(v.y * inv * g.y);
        u.z = f2tf32(v.z * inv * g.z);
        u.w = f2tf32(v.w * inv * g.w);
        *(uint4*)(y + base) = u;
    }
}

// ---------------------------------------------------------------------------
// Weight conversion: RNA-round all 4 weight matrices to tf32 buffers.
// ---------------------------------------------------------------------------
__global__ void convert_w_kernel(const float* __restrict__ wq,
                                 const float* __restrict__ wk,
                                 const float* __restrict__ wv,
                                 const float* __restrict__ wo)
{
    const size_t per = (size_t)DM * DM / 4;  // float4 per weight
    size_t i4 = (size_t)blockIdx.x * blockDim.x + threadIdx.x;
    int w = (int)(i4 / per);
    size_t off = (i4 - (size_t)w * per) * 4;
    const float* src = (w == 0) ? wq : (w == 1) ? wk : (w == 2) ? wv : wo;
    float* dst = (w == 0) ? g_wqc : (w == 1) ? g_wkc : (w == 2) ? g_wvc : g_woc;
    float4 v = *(const float4*)(src + off);
    uint4 u;
    u.x = f2tf32(v.x); u.y = f2tf32(v.y); u.z = f2tf32(v.z); u.w = f2tf32(v.w);
    *(uint4*)(dst + off) = u;
}

// ---------------------------------------------------------------------------
// TF32 tensor-core GEMM (NT): C[M,N] = A[M,K] * B[N,K]^T.
// Inputs MUST be pre-rounded tf32 (rna). Tile 128x128x16, 8 warps of 64x32.
// cp.async 4-stage pipeline; fragments via ldmatrix.x4; smem row stride 20
// words (20r mod 32 covers all 8 bank-groups -> conflict-free LDSM).
// ---------------------------------------------------------------------------
#define GSTR 20
#define ATW  (128 * GSTR)          // words per tile (2560)
#define STW  (2 * ATW)             // words per stage (A + B)
#define NST  4
#define GEMM_SMEM_BYTES (NST * STW * 4)   // 81920 B

__global__ void __launch_bounds__(256, 2)
sgemm_tc(const float* __restrict__ A, const float* __restrict__ B,
         float* __restrict__ C, int N, int K)
{
    extern __shared__ uint32_t gsm[];
    const uint32_t sbase = (uint32_t)__cvta_generic_to_shared(gsm);

    const int tid  = threadIdx.x;
    const int lane = tid & 31;
    const int warp = tid >> 5;
    const int g    = lane >> 2;
    const int tig  = lane & 3;
    const int m_base = (warp >> 2) * 64;
    const int n_base = (warp & 3) * 32;

    // cp.async staging: thread covers 2 chunks per tile
    const int r0 = tid >> 2;                 // rows 0..63
    const int c0 = (tid & 3) << 2;           // k word 0,4,8,12
    const int r1 = r0 + 64;                  // rows 64..127
    const float* Ag0 = A + (size_t)(blockIdx.y * 128 + r0) * K + c0;
    const float* Ag1 = A + (size_t)(blockIdx.y * 128 + r1) * K + c0;
    const float* Bg0 = B + (size_t)(blockIdx.x * 128 + r0) * K + c0;
    const float* Bg1 = B + (size_t)(blockIdx.x * 128 + r1) * K + c0;
    const uint32_t dA0 = (uint32_t)(r0 * GSTR + c0) * 4;
    const uint32_t dA1 = (uint32_t)(r1 * GSTR + c0) * 4;

    auto issue = [&](int kt) {
        const uint32_t st = sbase + (uint32_t)(kt & (NST - 1)) * (STW * 4);
        const int ko = kt << 4;
        cp16(st + dA0, Ag0 + ko);
        cp16(st + dA1, Ag1 + ko);
        cp16(st + ATW * 4 + dA0, Bg0 + ko);
        cp16(st + ATW * 4 + dA1, Bg1 + ko);
        CP_COMMIT();
    };

    float c[4][4][4];
#pragma unroll
    for (int mt = 0; mt < 4; mt++)
#pragma unroll
        for (int nt = 0; nt < 4; nt++)
#pragma unroll
            for (int i = 0; i < 4; i++) c[mt][nt][i] = 0.f;

    issue(0); issue(1); issue(2);

    // ldmatrix per-lane source rows/cols
    const int arow  = m_base + (lane & 15);
    const int acolh = (lane >> 2) & 4;
    const int brow  = n_base + (lane & 7) + ((lane >> 1) & 8);
    const int bcolh = (lane >> 1) & 4;

    const int KT = K >> 4;
    for (int kt = 0; kt < KT; kt++) {
        if (kt < KT - 2)      { CP_WAIT2(); }
        else if (kt == KT - 2){ CP_WAIT1(); }
        else                  { CP_WAIT0(); }
        __syncthreads();
        if (kt + 3 < KT) issue(kt + 3);

        const uint32_t tA = sbase + (uint32_t)(kt & (NST - 1)) * (STW * 4);
        const uint32_t tB = tA + ATW * 4;
#pragma unroll
        for (int kk = 0; kk < 2; kk++) {
            uint32_t a[4][4], b[2][4];
#pragma unroll
            for (int mt = 0; mt < 4; mt++)
                ldsm4(a[mt], tA + (uint32_t)((arow + mt * 16) * GSTR + kk * 8 + acolh) * 4);
            ldsm4(b[0], tB + (uint32_t)(brow * GSTR + kk * 8 + bcolh) * 4);
            ldsm4(b[1], tB + (uint32_t)((brow + 16) * GSTR + kk * 8 + bcolh) * 4);
#pragma unroll
            for (int mt = 0; mt < 4; mt++)
#pragma unroll
                for (int nt = 0; nt < 4; nt++) {
                    uint32_t bb[2] = { b[nt >> 1][(nt & 1) * 2],
                                       b[nt >> 1][(nt & 1) * 2 + 1] };
                    mma_tf32(c[mt][nt], a[mt], bb);
                }
        }
    }

    // Epilogue: c0:(g,2t) c1:(g,2t+1) c2:(g+8,2t) c3:(g+8,2t+1)
    const int crow = blockIdx.y * 128 + m_base + g;
    const int ccol = blockIdx.x * 128 + n_base + 2 * tig;
#pragma unroll
    for (int mt = 0; mt < 4; mt++) {
#pragma unroll
        for (int nt = 0; nt < 4; nt++) {
            const int row = crow + mt * 16;
            const int col = ccol + nt * 8;
            *(float2*)(C + (size_t)row * N + col) =
                make_float2(c[mt][nt][0], c[mt][nt][1]);
            *(float2*)(C + (size_t)(row + 8) * N + col) =
                make_float2(c[mt][nt][2], c[mt][nt][3]);
        }
    }
}

// ---------------------------------------------------------------------------
// RoPE (in-place) on a [S, NH, HD] fp32 buffer, position offset = CACHE
// ---------------------------------------------------------------------------
__global__ void rope_kernel(float* __restrict__ buf)
{
    int idx = blockIdx.x * blockDim.x + threadIdx.x;
    int i = idx & 63;
    int h = (idx >> 6) & (NH - 1);
    int s = idx >> 11;

    float pos = (float)(s + CACHE);
    float inv_freq = exp2f(-(float)i * (13.287712379549449f / 64.f));
    float ang = pos * inv_freq;
    float sn, cs;
    sincosf(ang, &sn, &cs);

    float* p = buf + ((size_t)(s * NH + h) * HD) + i;
    float x1 = p[0];
    float x2 = p[64];
    p[0]  = x1 * cs - x2 * sn;
    p[64] = x2 * cs + x1 * sn;
}

// ---------------------------------------------------------------------------
// Convert K/V (cache + new) into unified, RNA-rounded tf32 buffers [T,H,HD].
// ---------------------------------------------------------------------------
__global__ void convert_kv_kernel(const float* __restrict__ cache_k,
                                  const float* __restrict__ cache_v)
{
    const size_t i4 = (size_t)blockIdx.x * blockDim.x + threadIdx.x;
    const size_t elem = i4 * 4;
    const size_t t = elem / DM;
    const size_t rem = elem - t * DM;

    const float4* ks;
    const float4* vs;
    if (t < CACHE) {
        ks = (const float4*)(cache_k + elem);
        vs = (const float4*)(cache_v + elem);
    } else {
        size_t off = (t - CACHE) * DM + rem;
        ks = (const float4*)(g_k + off);
        vs = (const float4*)(g_v + off);
    }
    float4 k = *ks, v = *vs;
    uint4 ko, vo;
    ko.x = f2tf32(k.x); ko.y = f2tf32(k.y); ko.z = f2tf32(k.z); ko.w = f2tf32(k.w);
    vo.x = f2tf32(v.x); vo.y = f2tf32(v.y); vo.z = f2tf32(v.z); vo.w = f2tf32(v.w);
    *(uint4*)(g_kc + elem) = ko;
    *(uint4*)(g_vc + elem) = vo;
}

// ---------------------------------------------------------------------------
// Tensor-core flash attention (round-4 proven version; epilogue now emits
// RNA-rounded tf32 since g_at only feeds the output GEMM).
// ---------------------------------------------------------------------------
#define KQSTR 132
#define VSTR  136
#define PSTR  68

#define QS_WORDS (64 * KQSTR)
#define KS_WORDS (64 * KQSTR)
#define VS_WORDS (64 * VSTR)
#define PS_WORDS (64 * PSTR)

#define FLASH_SMEM_WORDS (QS_WORDS + 2*KS_WORDS + 2*VS_WORDS + PS_WORDS + 192)
#define FLASH_SMEM_BYTES (FLASH_SMEM_WORDS * 4)

__global__ void __launch_bounds__(256, 1)
flash_tc_kernel()
{
    extern __shared__ uint32_t fsm[];
    uint32_t* Qs  = fsm;
    uint32_t* Ks0 = Qs  + QS_WORDS;
    uint32_t* Ks1 = Ks0 + KS_WORDS;
    uint32_t* Vs0 = Ks1 + KS_WORDS;
    uint32_t* Vs1 = Vs0 + VS_WORDS;
    uint32_t* Ps  = Vs1 + VS_WORDS;
    float* m_s    = (float*)(Ps + PS_WORDS);
    float* l_s    = m_s + 64;
    float* salpha = l_s + 64;
    float* PsF    = (float*)Ps;

    const int h  = blockIdx.x;
    const int qt = (S_LEN / 64 - 1) - blockIdx.y;
    const int tid = threadIdx.x;
    const int lane = tid & 31;
    const int warp = tid >> 5;
    const int g    = lane >> 2;
    const int tig  = lane & 3;
    const int wr   = warp >> 1;
    const int wc   = warp & 1;
    const int m0   = wr * 16;

    const uint32_t ks0_a = (uint32_t)__cvta_generic_to_shared(Ks0);
    const uint32_t ks1_a = (uint32_t)__cvta_generic_to_shared(Ks1);
    const uint32_t vs0_a = (uint32_t)__cvta_generic_to_shared(Vs0);
    const uint32_t vs1_a = (uint32_t)__cvta_generic_to_shared(Vs1);

    const float qscale = 0.08838834764831845f;
#pragma unroll
    for (int it = 0; it < 8; it++) {
        int idx = it * 256 + tid;
        int r = idx >> 5;
        int c = (idx & 31) << 2;
        float4 v = *(const float4*)(g_q + (size_t)(qt * 64 + r) * DM + h * HD + c);
        uint4 u;
        u.x = f2tf32(v.x * qscale);
        u.y = f2tf32(v.y * qscale);
        u.z = f2tf32(v.z * qscale);
        u.w = f2tf32(v.w * qscale);
        *(uint4*)&Qs[r * KQSTR + c] = u;
    }
    if (tid < 64) { m_s[tid] = -1e30f; l_s[tid] = 0.f; }

    auto issue_kv = [&](int kt, int b) {
        const int t0 = kt * 64;
        const uint32_t ka = b ? ks1_a : ks0_a;
        const uint32_t va = b ? vs1_a : vs0_a;
#pragma unroll
        for (int it = 0; it < 8; it++) {
            int idx = it * 256 + tid;
            int r = idx >> 5;
            int c = (idx & 31) << 2;
            size_t off = (size_t)(t0 + r) * DM + h * HD + c;
            cp16(ka + (r * KQSTR + c) * 4, g_kc + off);
            cp16(va + (r * VSTR  + c) * 4, g_vc + off);
        }
        CP_COMMIT();
    };

    issue_kv(0, 0);

    float oacc[8][4];
#pragma unroll
    for (int nt = 0; nt < 8; nt++)
#pragma unroll
        for (int i = 0; i < 4; i++) oacc[nt][i] = 0.f;

    const int ntiles = 33 + qt;
    int p = 0;
    for (int kt = 0; kt < ntiles; kt++) {
        CP_WAIT0();
        __syncthreads();
        if (kt + 1 < ntiles) issue_kv(kt + 1, p ^ 1);

        const uint32_t* Kc = p ? Ks1 : Ks0;
        const uint32_t* Vc = p ? Vs1 : Vs0;

        float sacc[4][4];
#pragma unroll
        for (int nt = 0; nt < 4; nt++)
#pragma unroll
            for (int i = 0; i < 4; i++) sacc[nt][i] = 0.f;

        const uint32_t* Qb = Qs + (m0 + g) * KQSTR;
        const uint32_t* Kb = Kc + (wc * 32 + g) * KQSTR;
#pragma unroll
        for (int ks = 0; ks < 16; ks++) {
            const int k0 = ks * 8;
            uint32_t a[4];
            a[0] = Qb[k0 + tig];
            a[1] = Qb[8 * KQSTR + k0 + tig];
            a[2] = Qb[k0 + tig + 4];
            a[3] = Qb[8 * KQSTR + k0 + tig + 4];
#pragma unroll
            for (int nt = 0; nt < 4; nt++) {
                uint32_t b[2];
                b[0] = Kb[nt * 8 * KQSTR + k0 + tig];
                b[1] = Kb[nt * 8 * KQSTR + k0 + tig + 4];
                mma_tf32(sacc[nt], a, b);
            }
        }

        const bool diag = (kt == ntiles - 1);
        const int r0 = m0 + g, r1 = m0 + g + 8;
#pragma unroll
        for (int nt = 0; nt < 4; nt++) {
            int col = wc * 32 + nt * 8 + 2 * tig;
            float v0 = sacc[nt][0], v1 = sacc[nt][1];
            float v2 = sacc[nt][2], v3 = sacc[nt][3];
            if (diag) {
                if (col     > r0) v0 = -1e30f;
                if (col + 1 > r0) v1 = -1e30f;
                if (col     > r1) v2 = -1e30f;
                if (col + 1 > r1) v3 = -1e30f;
            }
            *(float2*)&PsF[r0 * PSTR + col] = make_float2(v0, v1);
            *(float2*)&PsF[r1 * PSTR + col] = make_float2(v2, v3);
        }
        __syncthreads();

        {
            const int row = tid >> 2;
            const int qd  = tid & 3;
            float* pr = PsF + row * PSTR + qd * 16;
            float4 x0 = *(float4*)(pr + 0);
            float4 x1 = *(float4*)(pr + 4);
            float4 x2 = *(float4*)(pr + 8);
            float4 x3 = *(float4*)(pr + 12);
            float mp = fmaxf(fmaxf(fmaxf(x0.x, x0.y), fmaxf(x0.z, x0.w)),
                             fmaxf(fmaxf(x1.x, x1.y), fmaxf(x1.z, x1.w)));
            mp = fmaxf(mp, fmaxf(fmaxf(fmaxf(x2.x, x2.y), fmaxf(x2.z, x2.w)),
                                 fmaxf(fmaxf(x3.x, x3.y), fmaxf(x3.z, x3.w))));
            mp = fmaxf(mp, __shfl_xor_sync(0xffffffffu, mp, 1));
            mp = fmaxf(mp, __shfl_xor_sync(0xffffffffu, mp, 2));
            const float mold = m_s[row];
            const float mx = fmaxf(mold, mp);
            float sum;
            {
                uint4 u;
                float s = 0.f;
                float p0, p1, p2, p3;
                p0 = __expf(x0.x - mx); p1 = __expf(x0.y - mx);
                p2 = __expf(x0.z - mx); p3 = __expf(x0.w - mx);
                s += (p0 + p1) + (p2 + p3);
                u.x = f2tf32(p0); u.y = f2tf32(p1); u.z = f2tf32(p2); u.w = f2tf32(p3);
                *(uint4*)(pr + 0) = u;
                p0 = __expf(x1.x - mx); p1 = __expf(x1.y - mx);
                p2 = __expf(x1.z - mx); p3 = __expf(x1.w - mx);
                s += (p0 + p1) + (p2 + p3);
                u.x = f2tf32(p0); u.y = f2tf32(p1); u.z = f2tf32(p2); u.w = f2tf32(p3);
                *(uint4*)(pr + 4) = u;
                p0 = __expf(x2.x - mx); p1 = __expf(x2.y - mx);
                p2 = __expf(x2.z - mx); p3 = __expf(x2.w - mx);
                s += (p0 + p1) + (p2 + p3);
                u.x = f2tf32(p0); u.y = f2tf32(p1); u.z = f2tf32(p2); u.w = f2tf32(p3);
                *(uint4*)(pr + 8) = u;
                p0 = __expf(x3.x - mx); p1 = __expf(x3.y - mx);
                p2 = __expf(x3.z - mx); p3 = __expf(x3.w - mx);
                s += (p0 + p1) + (p2 + p3);
                u.x = f2tf32(p0); u.y = f2tf32(p1); u.z = f2tf32(p2); u.w = f2tf32(p3);
                *(uint4*)(pr + 12) = u;
                sum = s;
            }
            sum += __shfl_xor_sync(0xffffffffu, sum, 1);
            sum += __shfl_xor_sync(0xffffffffu, sum, 2);
            __syncwarp();
            if (qd == 0) {
                float alpha = __expf(mold - mx);
                l_s[row] = l_s[row] * alpha + sum;
                m_s[row] = mx;
                salpha[row] = alpha;
            }
        }
        __syncthreads();

        {
            const float alo = salpha[m0 + g];
            const float ahi = salpha[m0 + g + 8];
#pragma unroll
            for (int nt = 0; nt < 8; nt++) {
                oacc[nt][0] *= alo; oacc[nt][1] *= alo;
                oacc[nt][2] *= ahi; oacc[nt][3] *= ahi;
            }
            const uint32_t* Pb = Ps + (m0 + g) * PSTR;
#pragma unroll
            for (int ks = 0; ks < 8; ks++) {
                const int k0 = ks * 8;
                uint32_t a[4];
                a[0] = Pb[k0 + tig];
                a[1] = Pb[8 * PSTR + k0 + tig];
                a[2] = Pb[k0 + tig + 4];
                a[3] = Pb[8 * PSTR + k0 + tig + 4];
                const uint32_t* V0 = Vc + (k0 + tig) * VSTR + wc * 64 + g;
                const uint32_t* V1 = V0 + 4 * VSTR;
#pragma unroll
                for (int nt = 0; nt < 8; nt++) {
                    uint32_t b[2];
                    b[0] = V0[nt * 8];
                    b[1] = V1[nt * 8];
                    mma_tf32(oacc[nt], a, b);
                }
            }
        }
        p ^= 1;
    }

    // ---- epilogue: O / l -> g_at (tf32-rounded: consumed only by GEMM) ----
    __syncthreads();
    const float ilo = 1.f / l_s[m0 + g];
    const float ihi = 1.f / l_s[m0 + g + 8];
    const int grow = qt * 64 + m0 + g;
#pragma unroll
    for (int nt = 0; nt < 8; nt++) {
        const int col = h * HD + wc * 64 + nt * 8 + 2 * tig;
        uint32_t* d0 = (uint32_t*)(g_at + (size_t)grow * DM + col);
        uint32_t* d1 = (uint32_t*)(g_at + (size_t)(grow + 8) * DM + col);
        d0[0] = f2tf32(oacc[nt][0] * ilo);
        d0[1] = f2tf32(oacc[nt][1] * ilo);
        d1[0] = f2tf32(oacc[nt][2] * ihi);
        d1[1] = f2tf32(oacc[nt][3] * ihi);
    }
}

// ---------------------------------------------------------------------------
// Launch
// ---------------------------------------------------------------------------
extern "C" void kernel_launch(void* const* d_in, const int* in_sizes, int n_in,
                              void* d_out, int out_size)
{
    (void)in_sizes; (void)n_in; (void)out_size;
    const float* xs      = (const float*)d_in[0];
    const float* cache_k = (const float*)d_in[1];
    const float* cache_v = (const float*)d_in[2];
    const float* norm_w  = (const float*)d_in[3];
    const float* wq      = (const float*)d_in[4];
    const float* wk      = (const float*)d_in[5];
    const float* wv      = (const float*)d_in[6];
    const float* wo      = (const float*)d_in[7];
    float* out = (float*)d_out;

    float *p_xn, *p_q, *p_k, *p_v, *p_at;
    float *p_wqc, *p_wkc, *p_wvc, *p_woc;
    cudaGetSymbolAddress((void**)&p_xn, g_xn);
    cudaGetSymbolAddress((void**)&p_q,  g_q);
    cudaGetSymbolAddress((void**)&p_k,  g_k);
    cudaGetSymbolAddress((void**)&p_v,  g_v);
    cudaGetSymbolAddress((void**)&p_at, g_at);
    cudaGetSymbolAddress((void**)&p_wqc, g_wqc);
    cudaGetSymbolAddress((void**)&p_wkc, g_wkc);
    cudaGetSymbolAddress((void**)&p_wvc, g_wvc);
    cudaGetSymbolAddress((void**)&p_woc, g_woc);

    cudaFuncSetAttribute(sgemm_tc,
                         cudaFuncAttributeMaxDynamicSharedMemorySize,
                         GEMM_SMEM_BYTES);
    cudaFuncSetAttribute(flash_tc_kernel,
                         cudaFuncAttributeMaxDynamicSharedMemorySize,
                         FLASH_SMEM_BYTES);

    // 1) RMSNorm (emits tf32-rounded xn)
    rmsnorm_kernel<<<S_LEN, 256>>>(xs, norm_w);

    // 2) Weight conversion to tf32 (all 4)
    {
        const size_t n4 = (size_t)4 * DM * DM / 4;
        convert_w_kernel<<<(unsigned)(n4 / 256), 256>>>(wq, wk, wv, wo);
    }

    // 3) QKV projections (cp.async + ldmatrix tensor-core GEMM)
    dim3 gg(DM / 128, S_LEN / 128);
    sgemm_tc<<<gg, 256, GEMM_SMEM_BYTES>>>(p_xn, p_wqc, p_q, DM, DM);
    sgemm_tc<<<gg, 256, GEMM_SMEM_BYTES>>>(p_xn, p_wkc, p_k, DM, DM);
    sgemm_tc<<<gg, 256, GEMM_SMEM_BYTES>>>(p_xn, p_wvc, p_v, DM, DM);

    // 4) RoPE on q and new k
    const int rope_threads = S_LEN * NH * 64;
    rope_kernel<<<rope_threads / 256, 256>>>(p_q);
    rope_kernel<<<rope_threads / 256, 256>>>(p_k);

    // 5) Unified + RNA-rounded K/V buffers
    {
        const size_t n4 = (size_t)TTOT * DM / 4;
        convert_kv_kernel<<<(unsigned)(n4 / 256), 256>>>(cache_k, cache_v);
    }

    // 6) Tensor-core flash attention
    flash_tc_kernel<<<dim3(NH, S_LEN / 64), 256, FLASH_SMEM_BYTES>>>();

    // 7) Output projection -> d_out
    sgemm_tc<<<gg, 256, GEMM_SMEM_BYTES>>>(p_at, p_woc, out, DM, DM);
}

// round 6
// speedup vs baseline: 3.8480x; 1.0687x over previous
#include <cuda_runtime.h>
#include <math.h>
#include <stdint.h>

// Problem constants (fixed shapes for this problem instance)
#define S_LEN  1024
#define DM     4096
#define NH     32
#define HD     128
#define CACHE  2048
#define TTOT   (CACHE + S_LEN)   // 3072 total kv positions

// Scratch (device globals: allocation-free rule)
__device__ float g_xn[S_LEN * DM];
__device__ float g_q [S_LEN * DM];
__device__ float g_k [S_LEN * DM];
__device__ float g_v [S_LEN * DM];
__device__ float g_at[S_LEN * DM];
__device__ float g_kc[(size_t)TTOT * DM];   // tf32-rounded unified K [T,H,HD]
__device__ float g_vc[(size_t)TTOT * DM];   // tf32-rounded unified V [T,H,HD]
__device__ float g_wqc[(size_t)DM * DM];    // tf32-rounded weights
__device__ float g_wkc[(size_t)DM * DM];
__device__ float g_wvc[(size_t)DM * DM];
__device__ float g_woc[(size_t)DM * DM];

// ---------------------------------------------------------------------------
// Common tensor-core helpers
// ---------------------------------------------------------------------------
__device__ __forceinline__ uint32_t f2tf32(float x) {
    uint32_t r;
    asm("cvt.rna.tf32.f32 %0, %1;" : "=r"(r) : "f"(x));
    return r;
}

__device__ __forceinline__ void mma_tf32(float c[4], const uint32_t a[4], const uint32_t b[2]) {
    asm volatile(
        "mma.sync.aligned.m16n8k8.row.col.f32.tf32.tf32.f32 "
        "{%0,%1,%2,%3}, {%4,%5,%6,%7}, {%8,%9}, {%0,%1,%2,%3};"
        : "+f"(c[0]), "+f"(c[1]), "+f"(c[2]), "+f"(c[3])
        : "r"(a[0]), "r"(a[1]), "r"(a[2]), "r"(a[3]), "r"(b[0]), "r"(b[1]));
}

__device__ __forceinline__ void ldsm4(uint32_t r[4], uint32_t addr) {
    asm volatile("ldmatrix.sync.aligned.m8n8.x4.shared.b16 {%0,%1,%2,%3}, [%4];"
        : "=r"(r[0]), "=r"(r[1]), "=r"(r[2]), "=r"(r[3]) : "r"(addr));
}

__device__ __forceinline__ void cp16(uint32_t dst, const void* src) {
    asm volatile("cp.async.cg.shared.global [%0], [%1], 16;" :: "r"(dst), "l"(src));
}
#define CP_COMMIT()  asm volatile("cp.async.commit_group;")
#define CP_WAIT0()   asm volatile("cp.async.wait_group 0;")
#define CP_WAIT1()   asm volatile("cp.async.wait_group 1;")

// ---------------------------------------------------------------------------
// RMSNorm: one block per row (4096 elems), 256 threads.
// Output is RNA-rounded to tf32 (it is only ever consumed as a GEMM A input).
// ---------------------------------------------------------------------------
__global__ void rmsnorm_kernel(const float* __restrict__ xs,
                               const float* __restrict__ w)
{
    const int row = blockIdx.x;
    const int tid = threadIdx.x;
    const float* x = xs + (size_t)row * DM;
    float* y = g_xn + (size_t)row * DM;

    float ss = 0.f;
#pragma unroll
    for (int i = 0; i < 4; i++) {
        float4 v = *(const float4*)(x + (i * 256 + tid) * 4);
        ss += v.x * v.x + v.y * v.y + v.z * v.z + v.w * v.w;
    }
#pragma unroll
    for (int off = 16; off; off >>= 1)
        ss += __shfl_xor_sync(0xffffffffu, ss, off);

    __shared__ float red[8];
    __shared__ float s_inv;
    if ((tid & 31) == 0) red[tid >> 5] = ss;
    __syncthreads();
    if (tid == 0) {
        float t = 0.f;
#pragma unroll
        for (int i = 0; i < 8; i++) t += red[i];
        s_inv = rsqrtf(t / (float)DM + 1e-6f);
    }
    __syncthreads();
    const float inv = s_inv;
#pragma unroll
    for (int i = 0; i < 4; i++) {
        int base = (i * 256 + tid) * 4;
        float4 v = *(const float4*)(x + base);
        float4 g = *(const float4*)(w + base);
        uint4 u;
        u.x = f2tf32(v.x * inv * g.x);
        u.y = f2tf32(v.y * inv * g.y);
        u.z = f2tf32(v.z * inv * g.z);
        u.w = f2tf32(v.w * inv * g.w);
        *(uint4*)(y + base) = u;
    }
}

// ---------------------------------------------------------------------------
// Weight conversion: RNA-round all 4 weight matrices to tf32 buffers.
// ---------------------------------------------------------------------------
__global__ void convert_w_kernel(const float* __restrict__ wq,
                                 const float* __restrict__ wk,
                                 const float* __restrict__ wv,
                                 const float* __restrict__ wo)
{
    const size_t per = (size_t)DM * DM / 4;  // float4 per weight
    size_t i4 = (size_t)blockIdx.x * blockDim.x + threadIdx.x;
    int w = (int)(i4 / per);
    size_t off = (i4 - (size_t)w * per) * 4;
    const float* src = (w == 0) ? wq : (w == 1) ? wk : (w == 2) ? wv : wo;
    float* dst = (w == 0) ? g_wqc : (w == 1) ? g_wkc : (w == 2) ? g_wvc : g_woc;
    float4 v = *(const float4*)(src + off);
    uint4 u;
    u.x = f2tf32(v.x); u.y = f2tf32(v.y); u.z = f2tf32(v.z); u.w = f2tf32(v.w);
    *(uint4*)(dst + off) = u;
}

// ---------------------------------------------------------------------------
// TF32 tensor-core GEMM (NT): C[M,N] = A[M,K] * B[N,K]^T.
// Inputs MUST be pre-rounded tf32 (rna). Tile 128x128x32, 8 warps of 64x32.
// cp.async 3-stage pipeline over k=32 slabs; fragments via ldmatrix.x4;
// smem row stride 36 words (36r mod 32 = 4r -> conflict-free LDSM).
// ---------------------------------------------------------------------------
#define GSTR 36
#define ATW  (128 * GSTR)          // words per tile (4608)
#define STW  (2 * ATW)             // words per stage (A + B)
#define NST  3
#define GEMM_SMEM_BYTES (NST * STW * 4)   // 110592 B

__global__ void __launch_bounds__(256, 2)
sgemm_tc(const float* __restrict__ A, const float* __restrict__ B,
         float* __restrict__ C, int N, int K)
{
    extern __shared__ uint32_t gsm[];
    const uint32_t sbase = (uint32_t)__cvta_generic_to_shared(gsm);

    const int tid  = threadIdx.x;
    const int lane = tid & 31;
    const int warp = tid >> 5;
    const int g    = lane >> 2;
    const int tig  = lane & 3;
    const int m_base = (warp >> 2) * 64;
    const int n_base = (warp & 3) * 32;

    // cp.async staging: tile = 128 rows x 32 words; 1024 chunks of 16B;
    // thread covers 4 chunks per tile: rows r0+{0,32,64,96}, k word c0.
    const int r0 = tid >> 3;                 // 0..31
    const int c0 = (tid & 7) << 2;           // 0,4,...,28
    const float* Ag = A + (size_t)(blockIdx.y * 128 + r0) * K + c0;
    const float* Bg = B + (size_t)(blockIdx.x * 128 + r0) * K + c0;
    const uint32_t d0 = (uint32_t)(r0 * GSTR + c0) * 4;
    const size_t gstep = (size_t)32 * K;          // 32 rows in gmem
    const uint32_t sstep = (uint32_t)(32 * GSTR) * 4;  // 32 rows in smem

    auto issue = [&](int kt) {
        const uint32_t st = sbase + (uint32_t)(kt % NST) * (STW * 4);
        const int ko = kt << 5;
        const float* a = Ag + ko;
        const float* b = Bg + ko;
#pragma unroll
        for (int it = 0; it < 4; it++) {
            cp16(st + d0 + it * sstep, a + it * gstep);
            cp16(st + ATW * 4 + d0 + it * sstep, b + it * gstep);
        }
        CP_COMMIT();
    };

    float c[4][4][4];
#pragma unroll
    for (int mt = 0; mt < 4; mt++)
#pragma unroll
        for (int nt = 0; nt < 4; nt++)
#pragma unroll
            for (int i = 0; i < 4; i++) c[mt][nt][i] = 0.f;

    issue(0); issue(1);

    // ldmatrix per-lane source rows/cols
    const int arow  = m_base + (lane & 15);
    const int acolh = (lane >> 2) & 4;
    const int brow  = n_base + (lane & 7) + ((lane >> 1) & 8);
    const int bcolh = (lane >> 1) & 4;

    const int KT = K >> 5;   // k=32 slabs
    for (int kt = 0; kt < KT; kt++) {
        if (kt + 1 < KT) { CP_WAIT1(); } else { CP_WAIT0(); }
        __syncthreads();
        if (kt + 2 < KT) issue(kt + 2);

        const uint32_t tA = sbase + (uint32_t)(kt % NST) * (STW * 4);
        const uint32_t tB = tA + ATW * 4;
#pragma unroll
        for (int kk = 0; kk < 4; kk++) {
            uint32_t a[4][4], b[2][4];
#pragma unroll
            for (int mt = 0; mt < 4; mt++)
                ldsm4(a[mt], tA + (uint32_t)((arow + mt * 16) * GSTR + kk * 8 + acolh) * 4);
            ldsm4(b[0], tB + (uint32_t)(brow * GSTR + kk * 8 + bcolh) * 4);
            ldsm4(b[1], tB + (uint32_t)((brow + 16) * GSTR + kk * 8 + bcolh) * 4);
#pragma unroll
            for (int mt = 0; mt < 4; mt++)
#pragma unroll
                for (int nt = 0; nt < 4; nt++) {
                    uint32_t bb[2] = { b[nt >> 1][(nt & 1) * 2],
                                       b[nt >> 1][(nt & 1) * 2 + 1] };
                    mma_tf32(c[mt][nt], a[mt], bb);
                }
        }
    }

    // Epilogue: c0:(g,2t) c1:(g,2t+1) c2:(g+8,2t) c3:(g+8,2t+1)
    const int crow = blockIdx.y * 128 + m_base + g;
    const int ccol = blockIdx.x * 128 + n_base + 2 * tig;
#pragma unroll
    for (int mt = 0; mt < 4; mt++) {
#pragma unroll
        for (int nt = 0; nt < 4; nt++) {
            const int row = crow + mt * 16;
            const int col = ccol + nt * 8;
            *(float2*)(C + (size_t)row * N + col) =
                make_float2(c[mt][nt][0], c[mt][nt][1]);
            *(float2*)(C + (size_t)(row + 8) * N + col) =
                make_float2(c[mt][nt][2], c[mt][nt][3]);
        }
    }
}

// ---------------------------------------------------------------------------
// RoPE (in-place) on a [S, NH, HD] fp32 buffer, position offset = CACHE
// ---------------------------------------------------------------------------
__global__ void rope_kernel(float* __restrict__ buf)
{
    int idx = blockIdx.x * blockDim.x + threadIdx.x;
    int i = idx & 63;
    int h = (idx >> 6) & (NH - 1);
    int s = idx >> 11;

    float pos = (float)(s + CACHE);
    float inv_freq = exp2f(-(float)i * (13.287712379549449f / 64.f));
    float ang = pos * inv_freq;
    float sn, cs;
    sincosf(ang, &sn, &cs);

    float* p = buf + ((size_t)(s * NH + h) * HD) + i;
    float x1 = p[0];
    float x2 = p[64];
    p[0]  = x1 * cs - x2 * sn;
    p[64] = x2 * cs + x1 * sn;
}

// ---------------------------------------------------------------------------
// Convert K/V (cache + new) into unified, RNA-rounded tf32 buffers [T,H,HD].
// ---------------------------------------------------------------------------
__global__ void convert_kv_kernel(const float* __restrict__ cache_k,
                                  const float* __restrict__ cache_v)
{
    const size_t i4 = (size_t)blockIdx.x * blockDim.x + threadIdx.x;
    const size_t elem = i4 * 4;
    const size_t t = elem / DM;
    const size_t rem = elem - t * DM;

    const float4* ks;
    const float4* vs;
    if (t < CACHE) {
        ks = (const float4*)(cache_k + elem);
        vs = (const float4*)(cache_v + elem);
    } else {
        size_t off = (t - CACHE) * DM + rem;
        ks = (const float4*)(g_k + off);
        vs = (const float4*)(g_v + off);
    }
    float4 k = *ks, v = *vs;
    uint4 ko, vo;
    ko.x = f2tf32(k.x); ko.y = f2tf32(k.y); ko.z = f2tf32(k.z); ko.w = f2tf32(k.w);
    vo.x = f2tf32(v.x); vo.y = f2tf32(v.y); vo.z = f2tf32(v.z); vo.w = f2tf32(v.w);
    *(uint4*)(g_kc + elem) = ko;
    *(uint4*)(g_vc + elem) = vo;
}

// ---------------------------------------------------------------------------
// Tensor-core flash attention. Fragments now via ldmatrix.x4 (Q/K/P);
// V fragments stay scalar LDS (already conflict-free). Numerics identical
// to round 5.
// ---------------------------------------------------------------------------
#define KQSTR 132
#define VSTR  136
#define PSTR  68

#define QS_WORDS (64 * KQSTR)
#define KS_WORDS (64 * KQSTR)
#define VS_WORDS (64 * VSTR)
#define PS_WORDS (64 * PSTR)

#define FLASH_SMEM_WORDS (QS_WORDS + 2*KS_WORDS + 2*VS_WORDS + PS_WORDS + 192)
#define FLASH_SMEM_BYTES (FLASH_SMEM_WORDS * 4)

__global__ void __launch_bounds__(256, 1)
flash_tc_kernel()
{
    extern __shared__ uint32_t fsm[];
    uint32_t* Qs  = fsm;
    uint32_t* Ks0 = Qs  + QS_WORDS;
    uint32_t* Ks1 = Ks0 + KS_WORDS;
    uint32_t* Vs0 = Ks1 + KS_WORDS;
    uint32_t* Vs1 = Vs0 + VS_WORDS;
    uint32_t* Ps  = Vs1 + VS_WORDS;
    float* m_s    = (float*)(Ps + PS_WORDS);
    float* l_s    = m_s + 64;
    float* salpha = l_s + 64;
    float* PsF    = (float*)Ps;

    const int h  = blockIdx.x;
    const int qt = (S_LEN / 64 - 1) - blockIdx.y;
    const int tid = threadIdx.x;
    const int lane = tid & 31;
    const int warp = tid >> 5;
    const int g    = lane >> 2;
    const int tig  = lane & 3;
    const int wr   = warp >> 1;
    const int wc   = warp & 1;
    const int m0   = wr * 16;

    const uint32_t qs_a  = (uint32_t)__cvta_generic_to_shared(Qs);
    const uint32_t ks0_a = (uint32_t)__cvta_generic_to_shared(Ks0);
    const uint32_t ks1_a = (uint32_t)__cvta_generic_to_shared(Ks1);
    const uint32_t vs0_a = (uint32_t)__cvta_generic_to_shared(Vs0);
    const uint32_t vs1_a = (uint32_t)__cvta_generic_to_shared(Vs1);
    const uint32_t ps_a  = (uint32_t)__cvta_generic_to_shared(Ps);

    const float qscale = 0.08838834764831845f;
#pragma unroll
    for (int it = 0; it < 8; it++) {
        int idx = it * 256 + tid;
        int r = idx >> 5;
        int c = (idx & 31) << 2;
        float4 v = *(const float4*)(g_q + (size_t)(qt * 64 + r) * DM + h * HD + c);
        uint4 u;
        u.x = f2tf32(v.x * qscale);
        u.y = f2tf32(v.y * qscale);
        u.z = f2tf32(v.z * qscale);
        u.w = f2tf32(v.w * qscale);
        *(uint4*)&Qs[r * KQSTR + c] = u;
    }
    if (tid < 64) { m_s[tid] = -1e30f; l_s[tid] = 0.f; }

    auto issue_kv = [&](int kt, int b) {
        const int t0 = kt * 64;
        const uint32_t ka = b ? ks1_a : ks0_a;
        const uint32_t va = b ? vs1_a : vs0_a;
#pragma unroll
        for (int it = 0; it < 8; it++) {
            int idx = it * 256 + tid;
            int r = idx >> 5;
            int c = (idx & 31) << 2;
            size_t off = (size_t)(t0 + r) * DM + h * HD + c;
            cp16(ka + (r * KQSTR + c) * 4, g_kc + off);
            cp16(va + (r * VSTR  + c) * 4, g_vc + off);
        }
        CP_COMMIT();
    };

    issue_kv(0, 0);

    float oacc[8][4];
#pragma unroll
    for (int nt = 0; nt < 8; nt++)
#pragma unroll
        for (int i = 0; i < 4; i++) oacc[nt][i] = 0.f;

    // ldmatrix lane mappings (same scheme as sgemm_tc, strides 132/68)
    const int arow  = m0 + (lane & 15);          // Q/P A-frag rows
    const int acolh = (lane >> 2) & 4;
    const int brow  = wc * 32 + (lane & 7) + ((lane >> 1) & 8);  // K B-frag rows
    const int bcolh = (lane >> 1) & 4;

    const int ntiles = 33 + qt;
    int p = 0;
    for (int kt = 0; kt < ntiles; kt++) {
        CP_WAIT0();
        __syncthreads();
        if (kt + 1 < ntiles) issue_kv(kt + 1, p ^ 1);

        const uint32_t ka = p ? ks1_a : ks0_a;
        const uint32_t* Vc = p ? Vs1 : Vs0;

        // ---- S = Q K^T (warp tile 16x32), ldmatrix fragments ----
        float sacc[4][4];
#pragma unroll
        for (int nt = 0; nt < 4; nt++)
#pragma unroll
            for (int i = 0; i < 4; i++) sacc[nt][i] = 0.f;

#pragma unroll
        for (int ks = 0; ks < 16; ks++) {
            const int k0 = ks * 8;
            uint32_t a[4], b[2][4];
            ldsm4(a, qs_a + (uint32_t)(arow * KQSTR + k0 + acolh) * 4);
            ldsm4(b[0], ka + (uint32_t)(brow * KQSTR + k0 + bcolh) * 4);
            ldsm4(b[1], ka + (uint32_t)((brow + 16) * KQSTR + k0 + bcolh) * 4);
#pragma unroll
            for (int nt = 0; nt < 4; nt++) {
                uint32_t bb[2] = { b[nt >> 1][(nt & 1) * 2],
                                   b[nt >> 1][(nt & 1) * 2 + 1] };
                mma_tf32(sacc[nt], a, bb);
            }
        }

        const bool diag = (kt == ntiles - 1);
        const int r0 = m0 + g, r1 = m0 + g + 8;
#pragma unroll
        for (int nt = 0; nt < 4; nt++) {
            int col = wc * 32 + nt * 8 + 2 * tig;
            float v0 = sacc[nt][0], v1 = sacc[nt][1];
            float v2 = sacc[nt][2], v3 = sacc[nt][3];
            if (diag) {
                if (col     > r0) v0 = -1e30f;
                if (col + 1 > r0) v1 = -1e30f;
                if (col     > r1) v2 = -1e30f;
                if (col + 1 > r1) v3 = -1e30f;
            }
            *(float2*)&PsF[r0 * PSTR + col] = make_float2(v0, v1);
            *(float2*)&PsF[r1 * PSTR + col] = make_float2(v2, v3);
        }
        __syncthreads();

        // ---- online softmax: 4 threads per row ----
        {
            const int row = tid >> 2;
            const int qd  = tid & 3;
            float* pr = PsF + row * PSTR + qd * 16;
            float4 x0 = *(float4*)(pr + 0);
            float4 x1 = *(float4*)(pr + 4);
            float4 x2 = *(float4*)(pr + 8);
            float4 x3 = *(float4*)(pr + 12);
            float mp = fmaxf(fmaxf(fmaxf(x0.x, x0.y), fmaxf(x0.z, x0.w)),
                             fmaxf(fmaxf(x1.x, x1.y), fmaxf(x1.z, x1.w)));
            mp = fmaxf(mp, fmaxf(fmaxf(fmaxf(x2.x, x2.y), fmaxf(x2.z, x2.w)),
                                 fmaxf(fmaxf(x3.x, x3.y), fmaxf(x3.z, x3.w))));
            mp = fmaxf(mp, __shfl_xor_sync(0xffffffffu, mp, 1));
            mp = fmaxf(mp, __shfl_xor_sync(0xffffffffu, mp, 2));
            const float mold = m_s[row];
            const float mx = fmaxf(mold, mp);
            float sum;
            {
                uint4 u;
                float s = 0.f;
                float p0, p1, p2, p3;
                p0 = __expf(x0.x - mx); p1 = __expf(x0.y - mx);
                p2 = __expf(x0.z - mx); p3 = __expf(x0.w - mx);
                s += (p0 + p1) + (p2 + p3);
                u.x = f2tf32(p0); u.y = f2tf32(p1); u.z = f2tf32(p2); u.w = f2tf32(p3);
                *(uint4*)(pr + 0) = u;
                p0 = __expf(x1.x - mx); p1 = __expf(x1.y - mx);
                p2 = __expf(x1.z - mx); p3 = __expf(x1.w - mx);
                s += (p0 + p1) + (p2 + p3);
                u.x = f2tf32(p0); u.y = f2tf32(p1); u.z = f2tf32(p2); u.w = f2tf32(p3);
                *(uint4*)(pr + 4) = u;
                p0 = __expf(x2.x - mx); p1 = __expf(x2.y - mx);
                p2 = __expf(x2.z - mx); p3 = __expf(x2.w - mx);
                s += (p0 + p1) + (p2 + p3);
                u.x = f2tf32(p0); u.y = f2tf32(p1); u.z = f2tf32(p2); u.w = f2tf32(p3);
                *(uint4*)(pr + 8) = u;
                p0 = __expf(x3.x - mx); p1 = __expf(x3.y - mx);
                p2 = __expf(x3.z - mx); p3 = __expf(x3.w - mx);
                s += (p0 + p1) + (p2 + p3);
                u.x = f2tf32(p0); u.y = f2tf32(p1); u.z = f2tf32(p2); u.w = f2tf32(p3);
                *(uint4*)(pr + 12) = u;
                sum = s;
            }
            sum += __shfl_xor_sync(0xffffffffu, sum, 1);
            sum += __shfl_xor_sync(0xffffffffu, sum, 2);
            __syncwarp();
            if (qd == 0) {
                float alpha = __expf(mold - mx);
                l_s[row] = l_s[row] * alpha + sum;
                m_s[row] = mx;
                salpha[row] = alpha;
            }
        }
        __syncthreads();

        // ---- rescale O, then O += P V (warp tile 16x64) ----
        {
            const float alo = salpha[m0 + g];
            const float ahi = salpha[m0 + g + 8];
#pragma unroll
            for (int nt = 0; nt < 8; nt++) {
                oacc[nt][0] *= alo; oacc[nt][1] *= alo;
                oacc[nt][2] *= ahi; oacc[nt][3] *= ahi;
            }
#pragma unroll
            for (int ks = 0; ks < 8; ks++) {
                const int k0 = ks * 8;
                uint32_t a[4];
                ldsm4(a, ps_a + (uint32_t)(arow * PSTR + k0 + acolh) * 4);
                const uint32_t* V0 = Vc + (k0 + tig) * VSTR + wc * 64 + g;
                const uint32_t* V1 = V0 + 4 * VSTR;
#pragma unroll
                for (int nt = 0; nt < 8; nt++) {
                    uint32_t b[2];
                    b[0] = V0[nt * 8];
                    b[1] = V1[nt * 8];
                    mma_tf32(oacc[nt], a, b);
                }
            }
        }
        p ^= 1;
    }

    // ---- epilogue: O / l -> g_at (tf32-rounded: consumed only by GEMM) ----
    __syncthreads();
    const float ilo = 1.f / l_s[m0 + g];
    const float ihi = 1.f / l_s[m0 + g + 8];
    const int grow = qt * 64 + m0 + g;
#pragma unroll
    for (int nt = 0; nt < 8; nt++) {
        const int col = h * HD + wc * 64 + nt * 8 + 2 * tig;
        uint32_t* d0 = (uint32_t*)(g_at + (size_t)grow * DM + col);
        uint32_t* d1 = (uint32_t*)(g_at + (size_t)(grow + 8) * DM + col);
        d0[0] = f2tf32(oacc[nt][0] * ilo);
        d0[1] = f2tf32(oacc[nt][1] * ilo);
        d1[0] = f2tf32(oacc[nt][2] * ihi);
        d1[1] = f2tf32(oacc[nt][3] * ihi);
    }
}

// ---------------------------------------------------------------------------
// Launch
// ---------------------------------------------------------------------------
extern "C" void kernel_launch(void* const* d_in, const int* in_sizes, int n_in,
                              void* d_out, int out_size)
{
    (void)in_sizes; (void)n_in; (void)out_size;
    const float* xs      = (const float*)d_in[0];
    const float* cache_k = (const float*)d_in[1];
    const float* cache_v = (const float*)d_in[2];
    const float* norm_w  = (const float*)d_in[3];
    const float* wq      = (const float*)d_in[4];
    const float* wk      = (const float*)d_in[5];
    const float* wv      = (const float*)d_in[6];
    const float* wo      = (const float*)d_in[7];
    float* out = (float*)d_out;

    float *p_xn, *p_q, *p_k, *p_v, *p_at;
    float *p_wqc, *p_wkc, *p_wvc, *p_woc;
    cudaGetSymbolAddress((void**)&p_xn, g_xn);
    cudaGetSymbolAddress((void**)&p_q,  g_q);
    cudaGetSymbolAddress((void**)&p_k,  g_k);
    cudaGetSymbolAddress((void**)&p_v,  g_v);
    cudaGetSymbolAddress((void**)&p_at, g_at);
    cudaGetSymbolAddress((void**)&p_wqc, g_wqc);
    cudaGetSymbolAddress((void**)&p_wkc, g_wkc);
    cudaGetSymbolAddress((void**)&p_wvc, g_wvc);
    cudaGetSymbolAddress((void**)&p_woc, g_woc);

    cudaFuncSetAttribute(sgemm_tc,
                         cudaFuncAttributeMaxDynamicSharedMemorySize,
                         GEMM_SMEM_BYTES);
    cudaFuncSetAttribute(flash_tc_kernel,
                         cudaFuncAttributeMaxDynamicSharedMemorySize,
                         FLASH_SMEM_BYTES);

    // 1) RMSNorm (emits tf32-rounded xn)
    rmsnorm_kernel<<<S_LEN, 256>>>(xs, norm_w);

    // 2) Weight conversion to tf32 (all 4)
    {
        const size_t n4 = (size_t)4 * DM * DM / 4;
        convert_w_kernel<<<(unsigned)(n4 / 256), 256>>>(wq, wk, wv, wo);
    }

    // 3) QKV projections (cp.async k32 pipeline + ldmatrix tensor-core GEMM)
    dim3 gg(DM / 128, S_LEN / 128);
    sgemm_tc<<<gg, 256, GEMM_SMEM_BYTES>>>(p_xn, p_wqc, p_q, DM, DM);
    sgemm_tc<<<gg, 256, GEMM_SMEM_BYTES>>>(p_xn, p_wkc, p_k, DM, DM);
    sgemm_tc<<<gg, 256, GEMM_SMEM_BYTES>>>(p_xn, p_wvc, p_v, DM, DM);

    // 4) RoPE on q and new k
    const int rope_threads = S_LEN * NH * 64;
    rope_kernel<<<rope_threads / 256, 256>>>(p_q);
    rope_kernel<<<rope_threads / 256, 256>>>(p_k);

    // 5) Unified + RNA-rounded K/V buffers
    {
        const size_t n4 = (size_t)TTOT * DM / 4;
        convert_kv_kernel<<<(unsigned)(n4 / 256), 256>>>(cache_k, cache_v);
    }

    // 6) Tensor-core flash attention
    flash_tc_kernel<<<dim3(NH, S_LEN / 64), 256, FLASH_SMEM_BYTES>>>();

    // 7) Output projection -> d_out
    sgemm_tc<<<gg, 256, GEMM_SMEM_BYTES>>>(p_at, p_woc, out, DM, DM);
}

// round 7
// speedup vs baseline: 3.8569x; 1.0023x over previous
#include <cuda_runtime.h>
#include <math.h>
#include <stdint.h>

// Problem constants (fixed shapes for this problem instance)
#define S_LEN  1024
#define DM     4096
#define NH     32
#define HD     128
#define CACHE  2048
#define TTOT   (CACHE + S_LEN)   // 3072 total kv positions

// Scratch (device globals: allocation-free rule)
__device__ float g_xn[S_LEN * DM];
__device__ float g_q [S_LEN * DM];
__device__ float g_k [S_LEN * DM];
__device__ float g_v [S_LEN * DM];
__device__ float g_at[S_LEN * DM];
__device__ float g_kc[(size_t)TTOT * DM];   // tf32-rounded unified K [T,H,HD]
__device__ float g_vc[(size_t)TTOT * DM];   // tf32-rounded unified V [T,H,HD]
__device__ float g_wqc[(size_t)DM * DM];    // tf32-rounded weights
__device__ float g_wkc[(size_t)DM * DM];
__device__ float g_wvc[(size_t)DM * DM];
__device__ float g_woc[(size_t)DM * DM];

// ---------------------------------------------------------------------------
// Common tensor-core helpers
// ---------------------------------------------------------------------------
__device__ __forceinline__ uint32_t f2tf32(float x) {
    uint32_t r;
    asm("cvt.rna.tf32.f32 %0, %1;" : "=r"(r) : "f"(x));
    return r;
}

__device__ __forceinline__ void mma_tf32(float c[4], const uint32_t a[4], const uint32_t b[2]) {
    asm volatile(
        "mma.sync.aligned.m16n8k8.row.col.f32.tf32.tf32.f32 "
        "{%0,%1,%2,%3}, {%4,%5,%6,%7}, {%8,%9}, {%0,%1,%2,%3};"
        : "+f"(c[0]), "+f"(c[1]), "+f"(c[2]), "+f"(c[3])
        : "r"(a[0]), "r"(a[1]), "r"(a[2]), "r"(a[3]), "r"(b[0]), "r"(b[1]));
}

__device__ __forceinline__ void ldsm4(uint32_t r[4], uint32_t addr) {
    asm volatile("ldmatrix.sync.aligned.m8n8.x4.shared.b16 {%0,%1,%2,%3}, [%4];"
        : "=r"(r[0]), "=r"(r[1]), "=r"(r[2]), "=r"(r[3]) : "r"(addr));
}

__device__ __forceinline__ void cp16(uint32_t dst, const void* src) {
    asm volatile("cp.async.cg.shared.global [%0], [%1], 16;" :: "r"(dst), "l"(src));
}
#define CP_COMMIT()  asm volatile("cp.async.commit_group;")
#define CP_WAIT0()   asm volatile("cp.async.wait_group 0;")
#define CP_WAIT1()   asm volatile("cp.async.wait_group 1;")

// ---------------------------------------------------------------------------
// RMSNorm: one block per row (4096 elems), 256 threads.
// Output is RNA-rounded to tf32 (it is only ever consumed as a GEMM A input).
// ---------------------------------------------------------------------------
__global__ void rmsnorm_kernel(const float* __restrict__ xs,
                               const float* __restrict__ w)
{
    const int row = blockIdx.x;
    const int tid = threadIdx.x;
    const float* x = xs + (size_t)row * DM;
    float* y = g_xn + (size_t)row * DM;

    float ss = 0.f;
#pragma unroll
    for (int i = 0; i < 4; i++) {
        float4 v = *(const float4*)(x + (i * 256 + tid) * 4);
        ss += v.x * v.x + v.y * v.y + v.z * v.z + v.w * v.w;
    }
#pragma unroll
    for (int off = 16; off; off >>= 1)
        ss += __shfl_xor_sync(0xffffffffu, ss, off);

    __shared__ float red[8];
    __shared__ float s_inv;
    if ((tid & 31) == 0) red[tid >> 5] = ss;
    __syncthreads();
    if (tid == 0) {
        float t = 0.f;
#pragma unroll
        for (int i = 0; i < 8; i++) t += red[i];
        s_inv = rsqrtf(t / (float)DM + 1e-6f);
    }
    __syncthreads();
    const float inv = s_inv;
#pragma unroll
    for (int i = 0; i < 4; i++) {
        int base = (i * 256 + tid) * 4;
        float4 v = *(const float4*)(x + base);
        float4 g = *(const float4*)(w + base);
        uint4 u;
        u.x = f2tf32(v.x * inv * g.x);
        u.y = f2tf32(v.y * inv * g.y);
        u.z = f2tf32(v.z * inv * g.z);
        u.w = f2tf32(v.w * inv * g.w);
        *(uint4*)(y + base) = u;
    }
}

// ---------------------------------------------------------------------------
// Weight conversion: RNA-round all 4 weight matrices to tf32 buffers.
// ---------------------------------------------------------------------------
__global__ void convert_w_kernel(const float* __restrict__ wq,
                                 const float* __restrict__ wk,
                                 const float* __restrict__ wv,
                                 const float* __restrict__ wo)
{
    const size_t per = (size_t)DM * DM / 4;  // float4 per weight
    size_t i4 = (size_t)blockIdx.x * blockDim.x + threadIdx.x;
    int w = (int)(i4 / per);
    size_t off = (i4 - (size_t)w * per) * 4;
    const float* src = (w == 0) ? wq : (w == 1) ? wk : (w == 2) ? wv : wo;
    float* dst = (w == 0) ? g_wqc : (w == 1) ? g_wkc : (w == 2) ? g_wvc : g_woc;
    float4 v = *(const float4*)(src + off);
    uint4 u;
    u.x = f2tf32(v.x); u.y = f2tf32(v.y); u.z = f2tf32(v.z); u.w = f2tf32(v.w);
    *(uint4*)(dst + off) = u;
}

// ---------------------------------------------------------------------------
// TF32 tensor-core GEMM (NT): C[M,N] = A[M,K] * B[N,K]^T.
// Inputs MUST be pre-rounded tf32 (rna). Tile 128x128x32, 8 warps of 64x32.
// cp.async 3-stage pipeline over k=32 slabs; fragments via ldmatrix.x4;
// smem row stride 36 words (36r mod 32 = 4r -> conflict-free LDSM).
// ---------------------------------------------------------------------------
#define GSTR 36
#define ATW  (128 * GSTR)          // words per tile (4608)
#define STW  (2 * ATW)             // words per stage (A + B)
#define NST  3
#define GEMM_SMEM_BYTES (NST * STW * 4)   // 110592 B

__global__ void __launch_bounds__(256, 2)
sgemm_tc(const float* __restrict__ A, const float* __restrict__ B,
         float* __restrict__ C, int N, int K)
{
    extern __shared__ uint32_t gsm[];
    const uint32_t sbase = (uint32_t)__cvta_generic_to_shared(gsm);

    const int tid  = threadIdx.x;
    const int lane = tid & 31;
    const int warp = tid >> 5;
    const int g    = lane >> 2;
    const int tig  = lane & 3;
    const int m_base = (warp >> 2) * 64;
    const int n_base = (warp & 3) * 32;

    // cp.async staging: tile = 128 rows x 32 words; 1024 chunks of 16B;
    // thread covers 4 chunks per tile: rows r0+{0,32,64,96}, k word c0.
    const int r0 = tid >> 3;                 // 0..31
    const int c0 = (tid & 7) << 2;           // 0,4,...,28
    const float* Ag = A + (size_t)(blockIdx.y * 128 + r0) * K + c0;
    const float* Bg = B + (size_t)(blockIdx.x * 128 + r0) * K + c0;
    const uint32_t d0 = (uint32_t)(r0 * GSTR + c0) * 4;
    const size_t gstep = (size_t)32 * K;          // 32 rows in gmem
    const uint32_t sstep = (uint32_t)(32 * GSTR) * 4;  // 32 rows in smem

    auto issue = [&](int kt) {
        const uint32_t st = sbase + (uint32_t)(kt % NST) * (STW * 4);
        const int ko = kt << 5;
        const float* a = Ag + ko;
        const float* b = Bg + ko;
#pragma unroll
        for (int it = 0; it < 4; it++) {
            cp16(st + d0 + it * sstep, a + it * gstep);
            cp16(st + ATW * 4 + d0 + it * sstep, b + it * gstep);
        }
        CP_COMMIT();
    };

    float c[4][4][4];
#pragma unroll
    for (int mt = 0; mt < 4; mt++)
#pragma unroll
        for (int nt = 0; nt < 4; nt++)
#pragma unroll
            for (int i = 0; i < 4; i++) c[mt][nt][i] = 0.f;

    issue(0); issue(1);

    // ldmatrix per-lane source rows/cols
    const int arow  = m_base + (lane & 15);
    const int acolh = (lane >> 2) & 4;
    const int brow  = n_base + (lane & 7) + ((lane >> 1) & 8);
    const int bcolh = (lane >> 1) & 4;

    const int KT = K >> 5;   // k=32 slabs
    for (int kt = 0; kt < KT; kt++) {
        if (kt + 1 < KT) { CP_WAIT1(); } else { CP_WAIT0(); }
        __syncthreads();
        if (kt + 2 < KT) issue(kt + 2);

        const uint32_t tA = sbase + (uint32_t)(kt % NST) * (STW * 4);
        const uint32_t tB = tA + ATW * 4;
#pragma unroll
        for (int kk = 0; kk < 4; kk++) {
            uint32_t a[4][4], b[2][4];
#pragma unroll
            for (int mt = 0; mt < 4; mt++)
                ldsm4(a[mt], tA + (uint32_t)((arow + mt * 16) * GSTR + kk * 8 + acolh) * 4);
            ldsm4(b[0], tB + (uint32_t)(brow * GSTR + kk * 8 + bcolh) * 4);
            ldsm4(b[1], tB + (uint32_t)((brow + 16) * GSTR + kk * 8 + bcolh) * 4);
#pragma unroll
            for (int mt = 0; mt < 4; mt++)
#pragma unroll
                for (int nt = 0; nt < 4; nt++) {
                    uint32_t bb[2] = { b[nt >> 1][(nt & 1) * 2],
                                       b[nt >> 1][(nt & 1) * 2 + 1] };
                    mma_tf32(c[mt][nt], a[mt], bb);
                }
        }
    }

    // Epilogue: c0:(g,2t) c1:(g,2t+1) c2:(g+8,2t) c3:(g+8,2t+1)
    const int crow = blockIdx.y * 128 + m_base + g;
    const int ccol = blockIdx.x * 128 + n_base + 2 * tig;
#pragma unroll
    for (int mt = 0; mt < 4; mt++) {
#pragma unroll
        for (int nt = 0; nt < 4; nt++) {
            const int row = crow + mt * 16;
            const int col = ccol + nt * 8;
            *(float2*)(C + (size_t)row * N + col) =
                make_float2(c[mt][nt][0], c[mt][nt][1]);
            *(float2*)(C + (size_t)(row + 8) * N + col) =
                make_float2(c[mt][nt][2], c[mt][nt][3]);
        }
    }
}

// ---------------------------------------------------------------------------
// RoPE (in-place) on a [S, NH, HD] fp32 buffer, position offset = CACHE
// ---------------------------------------------------------------------------
__global__ void rope_kernel(float* __restrict__ buf)
{
    int idx = blockIdx.x * blockDim.x + threadIdx.x;
    int i = idx & 63;
    int h = (idx >> 6) & (NH - 1);
    int s = idx >> 11;

    float pos = (float)(s + CACHE);
    float inv_freq = exp2f(-(float)i * (13.287712379549449f / 64.f));
    float ang = pos * inv_freq;
    float sn, cs;
    sincosf(ang, &sn, &cs);

    float* p = buf + ((size_t)(s * NH + h) * HD) + i;
    float x1 = p[0];
    float x2 = p[64];
    p[0]  = x1 * cs - x2 * sn;
    p[64] = x2 * cs + x1 * sn;
}

// ---------------------------------------------------------------------------
// Convert K/V (cache + new) into unified, RNA-rounded tf32 buffers [T,H,HD].
// ---------------------------------------------------------------------------
__global__ void convert_kv_kernel(const float* __restrict__ cache_k,
                                  const float* __restrict__ cache_v)
{
    const size_t i4 = (size_t)blockIdx.x * blockDim.x + threadIdx.x;
    const size_t elem = i4 * 4;
    const size_t t = elem / DM;
    const size_t rem = elem - t * DM;

    const float4* ks;
    const float4* vs;
    if (t < CACHE) {
        ks = (const float4*)(cache_k + elem);
        vs = (const float4*)(cache_v + elem);
    } else {
        size_t off = (t - CACHE) * DM + rem;
        ks = (const float4*)(g_k + off);
        vs = (const float4*)(g_v + off);
    }
    float4 k = *ks, v = *vs;
    uint4 ko, vo;
    ko.x = f2tf32(k.x); ko.y = f2tf32(k.y); ko.z = f2tf32(k.z); ko.w = f2tf32(k.w);
    vo.x = f2tf32(v.x); vo.y = f2tf32(v.y); vo.z = f2tf32(v.z); vo.w = f2tf32(v.w);
    *(uint4*)(g_kc + elem) = ko;
    *(uint4*)(g_vc + elem) = vo;
}

// ---------------------------------------------------------------------------
// Tensor-core flash attention. Fragments now via ldmatrix.x4 (Q/K/P);
// V fragments stay scalar LDS (already conflict-free). Numerics identical
// to round 5.
// ---------------------------------------------------------------------------
#define KQSTR 132
#define VSTR  136
#define PSTR  68

#define QS_WORDS (64 * KQSTR)
#define KS_WORDS (64 * KQSTR)
#define VS_WORDS (64 * VSTR)
#define PS_WORDS (64 * PSTR)

#define FLASH_SMEM_WORDS (QS_WORDS + 2*KS_WORDS + 2*VS_WORDS + PS_WORDS + 192)
#define FLASH_SMEM_BYTES (FLASH_SMEM_WORDS * 4)

__global__ void __launch_bounds__(256, 1)
flash_tc_kernel()
{
    extern __shared__ uint32_t fsm[];
    uint32_t* Qs  = fsm;
    uint32_t* Ks0 = Qs  + QS_WORDS;
    uint32_t* Ks1 = Ks0 + KS_WORDS;
    uint32_t* Vs0 = Ks1 + KS_WORDS;
    uint32_t* Vs1 = Vs0 + VS_WORDS;
    uint32_t* Ps  = Vs1 + VS_WORDS;
    float* m_s    = (float*)(Ps + PS_WORDS);
    float* l_s    = m_s + 64;
    float* salpha = l_s + 64;
    float* PsF    = (float*)Ps;

    const int h  = blockIdx.x;
    const int qt = (S_LEN / 64 - 1) - blockIdx.y;
    const int tid = threadIdx.x;
    const int lane = tid & 31;
    const int warp = tid >> 5;
    const int g    = lane >> 2;
    const int tig  = lane & 3;
    const int wr   = warp >> 1;
    const int wc   = warp & 1;
    const int m0   = wr * 16;

    const uint32_t qs_a  = (uint32_t)__cvta_generic_to_shared(Qs);
    const uint32_t ks0_a = (uint32_t)__cvta_generic_to_shared(Ks0);
    const uint32_t ks1_a = (uint32_t)__cvta_generic_to_shared(Ks1);
    const uint32_t vs0_a = (uint32_t)__cvta_generic_to_shared(Vs0);
    const uint32_t vs1_a = (uint32_t)__cvta_generic_to_shared(Vs1);
    const uint32_t ps_a  = (uint32_t)__cvta_generic_to_shared(Ps);

    const float qscale = 0.08838834764831845f;
#pragma unroll
    for (int it = 0; it < 8; it++) {
        int idx = it * 256 + tid;
        int r = idx >> 5;
        int c = (idx & 31) << 2;
        float4 v = *(const float4*)(g_q + (size_t)(qt * 64 + r) * DM + h * HD + c);
        uint4 u;
        u.x = f2tf32(v.x * qscale);
        u.y = f2tf32(v.y * qscale);
        u.z = f2tf32(v.z * qscale);
        u.w = f2tf32(v.w * qscale);
        *(uint4*)&Qs[r * KQSTR + c] = u;
    }
    if (tid < 64) { m_s[tid] = -1e30f; l_s[tid] = 0.f; }

    auto issue_kv = [&](int kt, int b) {
        const int t0 = kt * 64;
        const uint32_t ka = b ? ks1_a : ks0_a;
        const uint32_t va = b ? vs1_a : vs0_a;
#pragma unroll
        for (int it = 0; it < 8; it++) {
            int idx = it * 256 + tid;
            int r = idx >> 5;
            int c = (idx & 31) << 2;
            size_t off = (size_t)(t0 + r) * DM + h * HD + c;
            cp16(ka + (r * KQSTR + c) * 4, g_kc + off);
            cp16(va + (r * VSTR  + c) * 4, g_vc + off);
        }
        CP_COMMIT();
    };

    issue_kv(0, 0);

    float oacc[8][4];
#pragma unroll
    for (int nt = 0; nt < 8; nt++)
#pragma unroll
        for (int i = 0; i < 4; i++) oacc[nt][i] = 0.f;

    // ldmatrix lane mappings (same scheme as sgemm_tc, strides 132/68)
    const int arow  = m0 + (lane & 15);          // Q/P A-frag rows
    const int acolh = (lane >> 2) & 4;
    const int brow  = wc * 32 + (lane & 7) + ((lane >> 1) & 8);  // K B-frag rows
    const int bcolh = (lane >> 1) & 4;

    const int ntiles = 33 + qt;
    int p = 0;
    for (int kt = 0; kt < ntiles; kt++) {
        CP_WAIT0();
        __syncthreads();
        if (kt + 1 < ntiles) issue_kv(kt + 1, p ^ 1);

        const uint32_t ka = p ? ks1_a : ks0_a;
        const uint32_t* Vc = p ? Vs1 : Vs0;

        // ---- S = Q K^T (warp tile 16x32), ldmatrix fragments ----
        float sacc[4][4];
#pragma unroll
        for (int nt = 0; nt < 4; nt++)
#pragma unroll
            for (int i = 0; i < 4; i++) sacc[nt][i] = 0.f;

#pragma unroll
        for (int ks = 0; ks < 16; ks++) {
            const int k0 = ks * 8;
            uint32_t a[4], b[2][4];
            ldsm4(a, qs_a + (uint32_t)(arow * KQSTR + k0 + acolh) * 4);
            ldsm4(b[0], ka + (uint32_t)(brow * KQSTR + k0 + bcolh) * 4);
            ldsm4(b[1], ka + (uint32_t)((brow + 16) * KQSTR + k0 + bcolh) * 4);
#pragma unroll
            for (int nt = 0; nt < 4; nt++) {
                uint32_t bb[2] = { b[nt >> 1][(nt & 1) * 2],
                                   b[nt >> 1][(nt & 1) * 2 + 1] };
                mma_tf32(sacc[nt], a, bb);
            }
        }

        const bool diag = (kt == ntiles - 1);
        const int r0 = m0 + g, r1 = m0 + g + 8;
#pragma unroll
        for (int nt = 0; nt < 4; nt++) {
            int col = wc * 32 + nt * 8 + 2 * tig;
            float v0 = sacc[nt][0], v1 = sacc[nt][1];
            float v2 = sacc[nt][2], v3 = sacc[nt][3];
            if (diag) {
                if (col     > r0) v0 = -1e30f;
                if (col + 1 > r0) v1 = -1e30f;
                if (col     > r1) v2 = -1e30f;
                if (col + 1 > r1) v3 = -1e30f;
            }
            *(float2*)&PsF[r0 * PSTR + col] = make_float2(v0, v1);
            *(float2*)&PsF[r1 * PSTR + col] = make_float2(v2, v3);
        }
        __syncthreads();

        // ---- online softmax: 4 threads per row ----
        {
            const int row = tid >> 2;
            const int qd  = tid & 3;
            float* pr = PsF + row * PSTR + qd * 16;
            float4 x0 = *(float4*)(pr + 0);
            float4 x1 = *(float4*)(pr + 4);
            float4 x2 = *(float4*)(pr + 8);
            float4 x3 = *(float4*)(pr + 12);
            float mp = fmaxf(fmaxf(fmaxf(x0.x, x0.y), fmaxf(x0.z, x0.w)),
                             fmaxf(fmaxf(x1.x, x1.y), fmaxf(x1.z, x1.w)));
            mp = fmaxf(mp, fmaxf(fmaxf(fmaxf(x2.x, x2.y), fmaxf(x2.z, x2.w)),
                                 fmaxf(fmaxf(x3.x, x3.y), fmaxf(x3.z, x3.w))));
            mp = fmaxf(mp, __shfl_xor_sync(0xffffffffu, mp, 1));
            mp = fmaxf(mp, __shfl_xor_sync(0xffffffffu, mp, 2));
            const float mold = m_s[row];
            const float mx = fmaxf(mold, mp);
            float sum;
            {
                uint4 u;
                float s = 0.f;
                float p0, p1, p2, p3;
                p0 = __expf(x0.x - mx); p1 = __expf(x0.y - mx);
                p2 = __expf(x0.z - mx); p3 = __expf(x0.w - mx);
                s += (p0 + p1) + (p2 + p3);
                u.x = f2tf32(p0); u.y = f2tf32(p1); u.z = f2tf32(p2); u.w = f2tf32(p3);
                *(uint4*)(pr + 0) = u;
                p0 = __expf(x1.x - mx); p1 = __expf(x1.y - mx);
                p2 = __expf(x1.z - mx); p3 = __expf(x1.w - mx);
                s += (p0 + p1) + (p2 + p3);
                u.x = f2tf32(p0); u.y = f2tf32(p1); u.z = f2tf32(p2); u.w = f2tf32(p3);
                *(uint4*)(pr + 4) = u;
                p0 = __expf(x2.x - mx); p1 = __expf(x2.y - mx);
                p2 = __expf(x2.z - mx); p3 = __expf(x2.w - mx);
                s += (p0 + p1) + (p2 + p3);
                u.x = f2tf32(p0); u.y = f2tf32(p1); u.z = f2tf32(p2); u.w = f2tf32(p3);
                *(uint4*)(pr + 8) = u;
                p0 = __expf(x3.x - mx); p1 = __expf(x3.y - mx);
                p2 = __expf(x3.z - mx); p3 = __expf(x3.w - mx);
                s += (p0 + p1) + (p2 + p3);
                u.x = f2tf32(p0); u.y = f2tf32(p1); u.z = f2tf32(p2); u.w = f2tf32(p3);
                *(uint4*)(pr + 12) = u;
                sum = s;
            }
            sum += __shfl_xor_sync(0xffffffffu, sum, 1);
            sum += __shfl_xor_sync(0xffffffffu, sum, 2);
            __syncwarp();
            if (qd == 0) {
                float alpha = __expf(mold - mx);
                l_s[row] = l_s[row] * alpha + sum;
                m_s[row] = mx;
                salpha[row] = alpha;
            }
        }
        __syncthreads();

        // ---- rescale O, then O += P V (warp tile 16x64) ----
        {
            const float alo = salpha[m0 + g];
            const float ahi = salpha[m0 + g + 8];
#pragma unroll
            for (int nt = 0; nt < 8; nt++) {
                oacc[nt][0] *= alo; oacc[nt][1] *= alo;
                oacc[nt][2] *= ahi; oacc[nt][3] *= ahi;
            }
#pragma unroll
            for (int ks = 0; ks < 8; ks++) {
                const int k0 = ks * 8;
                uint32_t a[4];
                ldsm4(a, ps_a + (uint32_t)(arow * PSTR + k0 + acolh) * 4);
                const uint32_t* V0 = Vc + (k0 + tig) * VSTR + wc * 64 + g;
                const uint32_t* V1 = V0 + 4 * VSTR;
#pragma unroll
                for (int nt = 0; nt < 8; nt++) {
                    uint32_t b[2];
                    b[0] = V0[nt * 8];
                    b[1] = V1[nt * 8];
                    mma_tf32(oacc[nt], a, b);
                }
            }
        }
        p ^= 1;
    }

    // ---- epilogue: O / l -> g_at (tf32-rounded: consumed only by GEMM) ----
    __syncthreads();
    const float ilo = 1.f / l_s[m0 + g];
    const float ihi = 1.f / l_s[m0 + g + 8];
    const int grow = qt * 64 + m0 + g;
#pragma unroll
    for (int nt = 0; nt < 8; nt++) {
        const int col = h * HD + wc * 64 + nt * 8 + 2 * tig;
        uint32_t* d0 = (uint32_t*)(g_at + (size_t)grow * DM + col);
        uint32_t* d1 = (uint32_t*)(g_at + (size_t)(grow + 8) * DM + col);
        d0[0] = f2tf32(oacc[nt][0] * ilo);
        d0[1] = f2tf32(oacc[nt][1] * ilo);
        d1[0] = f2tf32(oacc[nt][2] * ihi);
        d1[1] = f2tf32(oacc[nt][3] * ihi);
    }
}

// ---------------------------------------------------------------------------
// Launch
// ---------------------------------------------------------------------------
extern "C" void kernel_launch(void* const* d_in, const int* in_sizes, int n_in,
                              void* d_out, int out_size)
{
    (void)in_sizes; (void)n_in; (void)out_size;
    const float* xs      = (const float*)d_in[0];
    const float* cache_k = (const float*)d_in[1];
    const float* cache_v = (const float*)d_in[2];
    const float* norm_w  = (const float*)d_in[3];
    const float* wq      = (const float*)d_in[4];
    const float* wk      = (const float*)d_in[5];
    const float* wv      = (const float*)d_in[6];
    const float* wo      = (const float*)d_in[7];
    float* out = (float*)d_out;

    float *p_xn, *p_q, *p_k, *p_v, *p_at;
    float *p_wqc, *p_wkc, *p_wvc, *p_woc;
    cudaGetSymbolAddress((void**)&p_xn, g_xn);
    cudaGetSymbolAddress((void**)&p_q,  g_q);
    cudaGetSymbolAddress((void**)&p_k,  g_k);
    cudaGetSymbolAddress((void**)&p_v,  g_v);
    cudaGetSymbolAddress((void**)&p_at, g_at);
    cudaGetSymbolAddress((void**)&p_wqc, g_wqc);
    cudaGetSymbolAddress((void**)&p_wkc, g_wkc);
    cudaGetSymbolAddress((void**)&p_wvc, g_wvc);
    cudaGetSymbolAddress((void**)&p_woc, g_woc);

    cudaFuncSetAttribute(sgemm_tc,
                         cudaFuncAttributeMaxDynamicSharedMemorySize,
                         GEMM_SMEM_BYTES);
    cudaFuncSetAttribute(flash_tc_kernel,
                         cudaFuncAttributeMaxDynamicSharedMemorySize,
                         FLASH_SMEM_BYTES);

    // 1) RMSNorm (emits tf32-rounded xn)
    rmsnorm_kernel<<<S_LEN, 256>>>(xs, norm_w);

    // 2) Weight conversion to tf32 (all 4)
    {
        const size_t n4 = (size_t)4 * DM * DM / 4;
        convert_w_kernel<<<(unsigned)(n4 / 256), 256>>>(wq, wk, wv, wo);
    }

    // 3) QKV projections (cp.async k32 pipeline + ldmatrix tensor-core GEMM)
    dim3 gg(DM / 128, S_LEN / 128);
    sgemm_tc<<<gg, 256, GEMM_SMEM_BYTES>>>(p_xn, p_wqc, p_q, DM, DM);
    sgemm_tc<<<gg, 256, GEMM_SMEM_BYTES>>>(p_xn, p_wkc, p_k, DM, DM);
    sgemm_tc<<<gg, 256, GEMM_SMEM_BYTES>>>(p_xn, p_wvc, p_v, DM, DM);

    // 4) RoPE on q and new k
    const int rope_threads = S_LEN * NH * 64;
    rope_kernel<<<rope_threads / 256, 256>>>(p_q);
    rope_kernel<<<rope_threads / 256, 256>>>(p_k);

    // 5) Unified + RNA-rounded K/V buffers
    {
        const size_t n4 = (size_t)TTOT * DM / 4;
        convert_kv_kernel<<<(unsigned)(n4 / 256), 256>>>(cache_k, cache_v);
    }

    // 6) Tensor-core flash attention
    flash_tc_kernel<<<dim3(NH, S_LEN / 64), 256, FLASH_SMEM_BYTES>>>();

    // 7) Output projection -> d_out
    sgemm_tc<<<gg, 256, GEMM_SMEM_BYTES>>>(p_at, p_woc, out, DM, DM);
}